// round 1
// baseline (speedup 1.0000x reference)
#include <cuda_runtime.h>
#include <math.h>

#define L 1024
#define D 768
#define NH 12
#define HD 64
#define LH (L*NH)

// ---------------- scratch (device globals; no allocation allowed) ----------
__device__ float g_q[L*D];
__device__ float g_k[L*D];
__device__ float g_v[L*D];
__device__ float g_u[L*D];
__device__ float g_usum[L*D];
__device__ float g_gate[L*36];
__device__ float g_s[LH];
__device__ float g_es[LH];
__device__ float g_al[LH];
__device__ float g_be[LH];
__device__ float g_ga[LH];
__device__ float g_ln[L*D];

// ---------------- generic NT GEMM body: C[M,N] = A[M,K] * B[N,K]^T ---------
// block tile 64x64, K-step 16, 256 threads, 4x4 frags. M assumed mult of 64.
__device__ __forceinline__ void gemm_nt_body(const float* __restrict__ A,
                                             const float* __restrict__ B,
                                             float* __restrict__ C,
                                             int N, int K) {
    __shared__ float As[16 * 68];
    __shared__ float Bs[16 * 68];
    const int tid = threadIdx.x;
    const int tx = tid & 15, ty = tid >> 4;
    const int m0 = blockIdx.y * 64, n0 = blockIdx.x * 64;
    const int lr = tid >> 2;          // 0..63 row within tile
    const int lk = (tid & 3) * 4;     // 0,4,8,12 k offset

    float acc[4][4];
#pragma unroll
    for (int i = 0; i < 4; i++)
#pragma unroll
        for (int j = 0; j < 4; j++) acc[i][j] = 0.f;

    const float* Ap = A + (size_t)(m0 + lr) * K + lk;
    const int brow = n0 + lr;
    const float* Bp = B + (size_t)brow * K + lk;
    const bool bv = brow < N;

    for (int kt = 0; kt < K; kt += 16) {
        float4 a = *(const float4*)(Ap + kt);
        float4 b = bv ? *(const float4*)(Bp + kt) : make_float4(0.f, 0.f, 0.f, 0.f);
        __syncthreads();
        As[(lk + 0) * 68 + lr] = a.x;
        As[(lk + 1) * 68 + lr] = a.y;
        As[(lk + 2) * 68 + lr] = a.z;
        As[(lk + 3) * 68 + lr] = a.w;
        Bs[(lk + 0) * 68 + lr] = b.x;
        Bs[(lk + 1) * 68 + lr] = b.y;
        Bs[(lk + 2) * 68 + lr] = b.z;
        Bs[(lk + 3) * 68 + lr] = b.w;
        __syncthreads();
#pragma unroll
        for (int kk = 0; kk < 16; kk++) {
            float4 av = *(const float4*)&As[kk * 68 + ty * 4];
            float4 bv4 = *(const float4*)&Bs[kk * 68 + tx * 4];
            float ar[4] = {av.x, av.y, av.z, av.w};
            float br[4] = {bv4.x, bv4.y, bv4.z, bv4.w};
#pragma unroll
            for (int i = 0; i < 4; i++)
#pragma unroll
                for (int j = 0; j < 4; j++) acc[i][j] = fmaf(ar[i], br[j], acc[i][j]);
        }
    }

#pragma unroll
    for (int i = 0; i < 4; i++) {
        int row = m0 + ty * 4 + i;
        int col0 = n0 + tx * 4;
        if (col0 + 3 < N) {
            float4 o = make_float4(acc[i][0], acc[i][1], acc[i][2], acc[i][3]);
            *(float4*)&C[(size_t)row * N + col0] = o;
        } else {
#pragma unroll
            for (int j = 0; j < 4; j++)
                if (col0 + j < N) C[(size_t)row * N + col0 + j] = acc[i][j];
        }
    }
}

__global__ void __launch_bounds__(256) gemm_qkvu(const float* __restrict__ X,
                                                 const float* __restrict__ Wq,
                                                 const float* __restrict__ Wk,
                                                 const float* __restrict__ Wv,
                                                 const float* __restrict__ Wu) {
    const float* W;
    float* C;
    switch (blockIdx.z) {
        case 0: W = Wq; C = g_q; break;
        case 1: W = Wk; C = g_k; break;
        case 2: W = Wv; C = g_v; break;
        default: W = Wu; C = g_u; break;
    }
    gemm_nt_body(X, W, C, D, D);
}

__global__ void __launch_bounds__(256) gemm_gate(const float* __restrict__ X,
                                                 const float* __restrict__ Wg) {
    gemm_nt_body(X, Wg, g_gate, 36, D);
}

__global__ void __launch_bounds__(256) gemm_out(const float* __restrict__ Wo,
                                                float* __restrict__ out) {
    gemm_nt_body(g_ln, Wo, out, D, D);
}

// ---------------- cumsum of u over L, per channel ---------------------------
__global__ void cumsum_u() {
    int c = blockIdx.x * blockDim.x + threadIdx.x;
    if (c >= D) return;
    float acc = 0.f;
#pragma unroll 4
    for (int l = 0; l < L; l++) {
        acc += g_u[l * D + c];
        g_usum[l * D + c] = acc;
    }
}

// ---------------- s_i = -(1/sqrt(d)) * u . bar_u ----------------------------
__global__ void compute_s(const float* __restrict__ pmu,
                          const float* __restrict__ plt) {
    int gw = (blockIdx.x * blockDim.x + threadIdx.x) >> 5;
    int lane = threadIdx.x & 31;
    if (gw >= LH) return;
    int l = gw / NH, h = gw % NH;
    float lt = expf(fminf(fmaxf(plt[h], -50.f), 30.f));
    float t = (float)(l + 1);
    float inv_den = 1.f / (lt + t);
    float acc = 0.f;
#pragma unroll
    for (int r = 0; r < 2; r++) {
        int i = lane + r * 32;
        float uu = g_u[l * D + h * HD + i];
        float bu = (lt * pmu[h * HD + i] + g_usum[l * D + h * HD + i]) * inv_den;
        acc = fmaf(uu, bu, acc);
    }
#pragma unroll
    for (int o = 16; o; o >>= 1) acc += __shfl_xor_sync(0xffffffffu, acc, o);
    if (lane == 0) g_s[l * NH + h] = -acc * 0.125f;  // 1/sqrt(64)
}

// ---------------- per-head: max, scans, gate coefficients -------------------
__global__ void __launch_bounds__(1024) head_scan() {
    __shared__ float she[1024];
    __shared__ float shp[1024];
    const int h = blockIdx.x;
    const int l = threadIdx.x;
    float s = g_s[l * NH + h];
    she[l] = s;
    __syncthreads();
    for (int off = 512; off > 0; off >>= 1) {
        if (l < off) she[l] = fmaxf(she[l], she[l + off]);
        __syncthreads();
    }
    float smax = she[0];
    __syncthreads();
    float e = expf(s - smax);
    float ev = e, pv = s;
    she[l] = ev;
    shp[l] = pv;
    __syncthreads();
    for (int off = 1; off < 1024; off <<= 1) {
        float ae = 0.f, ap = 0.f;
        if (l >= off) { ae = she[l - off]; ap = shp[l - off]; }
        __syncthreads();
        ev += ae;
        pv += ap;
        she[l] = ev;
        shp[l] = pv;
        __syncthreads();
    }
    float g1 = g_gate[l * 36 + h * 3 + 0];
    float gh = g_gate[l * 36 + h * 3 + 1];
    float s1 = 1.f / (1.f + expf(-g1));
    float shg = 1.f / (1.f + expf(-gh));
    float t = (float)(l + 1);
    float a = shg / (ev + 1e-12f);
    float b = (s1 - shg) / t;
    float gm = -(b * pv + shg) / t;
    int o = l * NH + h;
    g_es[o] = e;
    g_al[o] = a;
    g_be[o] = b;
    g_ga[o] = gm;
}

// ---------------- RoPE + L2 normalize on q, k -------------------------------
__global__ void rope_norm() {
    int gw = (blockIdx.x * blockDim.x + threadIdx.x) >> 5;
    int lane = threadIdx.x & 31;
    if (gw >= LH) return;
    int l = gw / NH, h = gw % NH;
    int base = l * D + h * HD;
    int i0 = lane >> 1;
    // inv_freq = 10000^(-i/32); angle computed in fp64 for phase accuracy
    const double LN1E4_32 = 0.28782313662425572;  // ln(10000)/32
    double f0 = exp(-(double)i0 * LN1E4_32);
    double f1 = exp(-(double)(i0 + 16) * LN1E4_32);
    double a0 = (double)l * f0;
    double a1 = (double)l * f1;
    float c0 = (float)cos(a0), sn0 = (float)sin(a0);
    float c1 = (float)cos(a1), sn1 = (float)sin(a1);

    // q
    {
        float x0 = g_q[base + lane], x1 = g_q[base + lane + 32];
        float r0 = x0 * c0 - x1 * sn0;
        float r1 = x1 * c1 + x0 * sn1;
        float nn = r0 * r0 + r1 * r1;
#pragma unroll
        for (int o = 16; o; o >>= 1) nn += __shfl_xor_sync(0xffffffffu, nn, o);
        float inv = 1.f / fmaxf(sqrtf(nn), 1e-12f);
        g_q[base + lane] = r0 * inv;
        g_q[base + lane + 32] = r1 * inv;
    }
    // k
    {
        float x0 = g_k[base + lane], x1 = g_k[base + lane + 32];
        float r0 = x0 * c0 - x1 * sn0;
        float r1 = x1 * c1 + x0 * sn1;
        float nn = r0 * r0 + r1 * r1;
#pragma unroll
        for (int o = 16; o; o >>= 1) nn += __shfl_xor_sync(0xffffffffu, nn, o);
        float inv = 1.f / fmaxf(sqrtf(nn), 1e-12f);
        g_k[base + lane] = r0 * inv;
        g_k[base + lane + 32] = r1 * inv;
    }
}

// ---------------- weighted causal attention + fused LayerNorm ---------------
// out_l = sum_{j<=l} (q_l.k_j) * (al_l*es_j + be_l*s_j + ga_l) * v_j
// dynamic smem: Qs[64][68] | KSs[64][68] (K tile, reused as S^T) | Vs[64][64]
#define ATTN_SMEM ((2 * 64 * 68 + 64 * 64) * 4)

__global__ void __launch_bounds__(256) attn_kernel() {
    extern __shared__ float smem[];
    float* Qs = smem;                 // [d][m], stride 68
    float* KSs = smem + 64 * 68;      // [d][j] then reused as S^T [j][m]
    float* Vs = smem + 2 * 64 * 68;   // [j][e], stride 64
    __shared__ float cA[64], cB[64], cG[64], sES[64], sS[64];

    const int h = blockIdx.y;
    const int lt = 15 - blockIdx.x;  // heavy tiles first
    const int l0 = lt * 64;
    const int tid = threadIdx.x;
    const int tx = tid & 15, ty = tid >> 4;

    // load Q tile transposed: Qs[d][m]
#pragma unroll
    for (int it = 0; it < 4; it++) {
        int idx = tid + it * 256;
        int row = idx >> 4;
        int c4 = (idx & 15) << 2;
        float4 x = *(const float4*)(g_q + (l0 + row) * D + h * HD + c4);
        Qs[(c4 + 0) * 68 + row] = x.x;
        Qs[(c4 + 1) * 68 + row] = x.y;
        Qs[(c4 + 2) * 68 + row] = x.z;
        Qs[(c4 + 3) * 68 + row] = x.w;
    }
    if (tid < 64) {
        cA[tid] = g_al[(l0 + tid) * NH + h];
        cB[tid] = g_be[(l0 + tid) * NH + h];
        cG[tid] = g_ga[(l0 + tid) * NH + h];
    }

    float oacc[4][4];
#pragma unroll
    for (int i = 0; i < 4; i++)
#pragma unroll
        for (int j = 0; j < 4; j++) oacc[i][j] = 0.f;

    for (int jt = 0; jt <= lt; jt++) {
        const int j0 = jt * 64;
        __syncthreads();  // previous O-stage done (and Q-load visible on iter 0)
        // load K transposed, V natural, per-j scalars
#pragma unroll
        for (int it = 0; it < 4; it++) {
            int idx = tid + it * 256;
            int row = idx >> 4;
            int c4 = (idx & 15) << 2;
            float4 xk = *(const float4*)(g_k + (j0 + row) * D + h * HD + c4);
            KSs[(c4 + 0) * 68 + row] = xk.x;
            KSs[(c4 + 1) * 68 + row] = xk.y;
            KSs[(c4 + 2) * 68 + row] = xk.z;
            KSs[(c4 + 3) * 68 + row] = xk.w;
            float4 xv = *(const float4*)(g_v + (j0 + row) * D + h * HD + c4);
            *(float4*)&Vs[row * 64 + c4] = xv;
        }
        if (tid < 64) {
            sES[tid] = g_es[(j0 + tid) * NH + h];
            sS[tid] = g_s[(j0 + tid) * NH + h];
        }
        __syncthreads();

        // S = Q K^T (fragmented)
        float sacc[4][4];
#pragma unroll
        for (int i = 0; i < 4; i++)
#pragma unroll
            for (int j = 0; j < 4; j++) sacc[i][j] = 0.f;
#pragma unroll 8
        for (int kk = 0; kk < 64; kk++) {
            float4 av = *(const float4*)&Qs[kk * 68 + ty * 4];
            float4 bv = *(const float4*)&KSs[kk * 68 + tx * 4];
            float ar[4] = {av.x, av.y, av.z, av.w};
            float br[4] = {bv.x, bv.y, bv.z, bv.w};
#pragma unroll
            for (int i = 0; i < 4; i++)
#pragma unroll
                for (int j = 0; j < 4; j++) sacc[i][j] = fmaf(ar[i], br[j], sacc[i][j]);
        }
        __syncthreads();  // K reads done; safe to overwrite KSs with S^T

        // weight + causal mask, write S^T into KSs: KSs[c][r]
#pragma unroll
        for (int i = 0; i < 4; i++) {
            int r = ty * 4 + i;
            int gl = l0 + r;
            float Ar = cA[r], Br = cB[r], Gr = cG[r];
#pragma unroll
            for (int j = 0; j < 4; j++) {
                int c = tx * 4 + j;
                int gj = j0 + c;
                float w = Ar * sES[c] + Br * sS[c] + Gr;
                KSs[c * 68 + r] = (gj <= gl) ? sacc[i][j] * w : 0.f;
            }
        }
        __syncthreads();

        // O += S V
#pragma unroll 8
        for (int c = 0; c < 64; c++) {
            float4 av = *(const float4*)&KSs[c * 68 + ty * 4];
            float4 bv = *(const float4*)&Vs[c * 64 + tx * 4];
            float ar[4] = {av.x, av.y, av.z, av.w};
            float br[4] = {bv.x, bv.y, bv.z, bv.w};
#pragma unroll
            for (int i = 0; i < 4; i++)
#pragma unroll
                for (int j = 0; j < 4; j++) oacc[i][j] = fmaf(ar[i], br[j], oacc[i][j]);
        }
    }

    // fused LayerNorm over head dim (row r spread over 16 lanes of a half-warp)
#pragma unroll
    for (int i = 0; i < 4; i++) {
        float sum = oacc[i][0] + oacc[i][1] + oacc[i][2] + oacc[i][3];
#pragma unroll
        for (int o = 8; o; o >>= 1) sum += __shfl_xor_sync(0xffffffffu, sum, o);
        float mean = sum * (1.f / 64.f);
        float d0 = oacc[i][0] - mean, d1 = oacc[i][1] - mean;
        float d2 = oacc[i][2] - mean, d3 = oacc[i][3] - mean;
        float vs = d0 * d0 + d1 * d1 + d2 * d2 + d3 * d3;
#pragma unroll
        for (int o = 8; o; o >>= 1) vs += __shfl_xor_sync(0xffffffffu, vs, o);
        float inv = rsqrtf(vs * (1.f / 64.f) + 1e-5f);
        float4 ov = make_float4(d0 * inv, d1 * inv, d2 * inv, d3 * inv);
        *(float4*)&g_ln[(l0 + ty * 4 + i) * D + h * HD + tx * 4] = ov;
    }
}

// ---------------- launch ----------------------------------------------------
extern "C" void kernel_launch(void* const* d_in, const int* in_sizes, int n_in,
                              void* d_out, int out_size) {
    const float* X = (const float*)d_in[0];
    const float* Wq = (const float*)d_in[1];
    const float* Wk = (const float*)d_in[2];
    const float* Wv = (const float*)d_in[3];
    const float* Wu = (const float*)d_in[4];
    const float* Wg = (const float*)d_in[5];
    const float* Wo = (const float*)d_in[6];
    const float* pmu = (const float*)d_in[7];
    const float* plt = (const float*)d_in[8];
    float* out = (float*)d_out;

    cudaFuncSetAttribute(attn_kernel, cudaFuncAttributeMaxDynamicSharedMemorySize,
                         ATTN_SMEM);

    // projections
    gemm_qkvu<<<dim3(D / 64, L / 64, 4), 256>>>(X, Wq, Wk, Wv, Wu);
    gemm_gate<<<dim3(1, L / 64), 256>>>(X, Wg);

    // logits pipeline
    cumsum_u<<<(D + 127) / 128, 128>>>();
    compute_s<<<(LH * 32 + 255) / 256, 256>>>(pmu, plt);
    head_scan<<<NH, 1024>>>();

    // RoPE + normalize
    rope_norm<<<(LH * 32 + 255) / 256, 256>>>();

    // attention + fused LayerNorm
    attn_kernel<<<dim3(16, NH), 256, ATTN_SMEM>>>();

    // output projection
    gemm_out<<<dim3(D / 64, L / 64), 256>>>(Wo, out);
}

// round 2
// speedup vs baseline: 1.2662x; 1.2662x over previous
#include <cuda_runtime.h>
#include <cuda_bf16.h>
#include <mma.h>
#include <math.h>

using namespace nvcuda;

#define L 1024
#define D 768
#define NH 12
#define HD 64
#define LH (L*NH)

// ---------------- scratch (device globals; no allocation allowed) ----------
__device__ float g_q[L*D];
__device__ float g_k[L*D];
__device__ float g_v[L*D];
__device__ float g_u[L*D];
__device__ float g_usum[L*D];
__device__ float g_gate[L*36];
__device__ float g_s[LH];
__device__ float g_es[LH];
__device__ float g_al[LH];
__device__ float g_be[LH];
__device__ float g_ga[LH];

// split-bf16 buffers
__device__ __nv_bfloat16 g_Xh[L*D];
__device__ __nv_bfloat16 g_Xl[L*D];
__device__ __nv_bfloat16 g_Wh[5*D*D];   // Wq,Wk,Wv,Wu,Wo
__device__ __nv_bfloat16 g_Wl[5*D*D];
__device__ __nv_bfloat16 g_lnh[L*D];
__device__ __nv_bfloat16 g_lnl[L*D];

// ---------------- fp32 -> (hi, lo) bf16 conversion --------------------------
__global__ void convert_inputs(const float* __restrict__ X,
                               const float* __restrict__ Wq,
                               const float* __restrict__ Wk,
                               const float* __restrict__ Wv,
                               const float* __restrict__ Wu,
                               const float* __restrict__ Wo) {
    int z = blockIdx.y;
    const float* src;
    __nv_bfloat16 *dh, *dl;
    int n;
    if (z == 0) { src = X; dh = g_Xh; dl = g_Xl; n = L * D; }
    else {
        const float* ws[5] = {Wq, Wk, Wv, Wu, Wo};
        src = ws[z - 1];
        dh = g_Wh + (z - 1) * D * D;
        dl = g_Wl + (z - 1) * D * D;
        n = D * D;
    }
    for (int i = blockIdx.x * blockDim.x + threadIdx.x; i < n;
         i += gridDim.x * blockDim.x) {
        float v = src[i];
        __nv_bfloat16 h = __float2bfloat16(v);
        dh[i] = h;
        dl[i] = __float2bfloat16(v - __bfloat162float(h));
    }
}

// ---------------- split-bf16 tensor-core GEMM -------------------------------
// C[1024,768] = A[1024,768] * B[768,768]^T via 3 passes:
//   Ah*Bh + Al*Bh + Ah*Bl   (drops Al*Bl ~ 2^-16 rel)
#define BM 128
#define BN 64
#define BK 64
#define LDS_ 72

__device__ __forceinline__ void gemm_bf16_body(
    const __nv_bfloat16* __restrict__ Ah, const __nv_bfloat16* __restrict__ Al,
    const __nv_bfloat16* __restrict__ Bh, const __nv_bfloat16* __restrict__ Bl,
    float* __restrict__ C) {
    __shared__ __nv_bfloat16 As[BM * LDS_];
    __shared__ __nv_bfloat16 Bs[BN * LDS_];
    const int tid = threadIdx.x;
    const int warp = tid >> 5;
    const int wm = warp >> 1, wn = warp & 1;
    const int m0 = blockIdx.y * BM, n0 = blockIdx.x * BN;

    wmma::fragment<wmma::accumulator, 16, 16, 16, float> acc[2][2];
#pragma unroll
    for (int i = 0; i < 2; i++)
#pragma unroll
        for (int j = 0; j < 2; j++) wmma::fill_fragment(acc[i][j], 0.f);

#pragma unroll 1
    for (int seg = 0; seg < 3; seg++) {
        const __nv_bfloat16* A = (seg == 1) ? Al : Ah;
        const __nv_bfloat16* B = (seg == 2) ? Bl : Bh;
#pragma unroll 1
        for (int kt = 0; kt < D; kt += BK) {
            __syncthreads();
#pragma unroll
            for (int i = 0; i < 4; i++) {
                int idx = tid + i * 256;
                int r = idx >> 3;
                int c = (idx & 7) * 8;
                *(uint4*)&As[r * LDS_ + c] =
                    *(const uint4*)&A[(size_t)(m0 + r) * D + kt + c];
            }
#pragma unroll
            for (int i = 0; i < 2; i++) {
                int idx = tid + i * 256;
                int r = idx >> 3;
                int c = (idx & 7) * 8;
                *(uint4*)&Bs[r * LDS_ + c] =
                    *(const uint4*)&B[(size_t)(n0 + r) * D + kt + c];
            }
            __syncthreads();
#pragma unroll
            for (int kk = 0; kk < BK; kk += 16) {
                wmma::fragment<wmma::matrix_a, 16, 16, 16, __nv_bfloat16,
                               wmma::row_major> a0, a1;
                wmma::fragment<wmma::matrix_b, 16, 16, 16, __nv_bfloat16,
                               wmma::col_major> b0, b1;
                wmma::load_matrix_sync(a0, &As[(wm * 32) * LDS_ + kk], LDS_);
                wmma::load_matrix_sync(a1, &As[(wm * 32 + 16) * LDS_ + kk], LDS_);
                wmma::load_matrix_sync(b0, &Bs[(wn * 32) * LDS_ + kk], LDS_);
                wmma::load_matrix_sync(b1, &Bs[(wn * 32 + 16) * LDS_ + kk], LDS_);
                wmma::mma_sync(acc[0][0], a0, b0, acc[0][0]);
                wmma::mma_sync(acc[0][1], a0, b1, acc[0][1]);
                wmma::mma_sync(acc[1][0], a1, b0, acc[1][0]);
                wmma::mma_sync(acc[1][1], a1, b1, acc[1][1]);
            }
        }
    }

#pragma unroll
    for (int i = 0; i < 2; i++)
#pragma unroll
        for (int j = 0; j < 2; j++)
            wmma::store_matrix_sync(
                &C[(size_t)(m0 + wm * 32 + i * 16) * D + n0 + wn * 32 + j * 16],
                acc[i][j], D, wmma::mem_row_major);
}

__global__ void __launch_bounds__(256) gemm_qkvu_tc() {
    int z = blockIdx.z;
    float* Cs[4] = {g_q, g_k, g_v, g_u};
    gemm_bf16_body(g_Xh, g_Xl, g_Wh + (size_t)z * D * D, g_Wl + (size_t)z * D * D,
                   Cs[z]);
}

__global__ void __launch_bounds__(256) gemm_out_tc(float* __restrict__ out) {
    gemm_bf16_body(g_lnh, g_lnl, g_Wh + (size_t)4 * D * D,
                   g_Wl + (size_t)4 * D * D, out);
}

// ---------------- fp32 NT GEMM (kept for small gate matmul) -----------------
__device__ __forceinline__ void gemm_nt_body(const float* __restrict__ A,
                                             const float* __restrict__ B,
                                             float* __restrict__ C,
                                             int N, int K) {
    __shared__ float As[16 * 68];
    __shared__ float Bs[16 * 68];
    const int tid = threadIdx.x;
    const int tx = tid & 15, ty = tid >> 4;
    const int m0 = blockIdx.y * 64, n0 = blockIdx.x * 64;
    const int lr = tid >> 2;
    const int lk = (tid & 3) * 4;

    float acc[4][4];
#pragma unroll
    for (int i = 0; i < 4; i++)
#pragma unroll
        for (int j = 0; j < 4; j++) acc[i][j] = 0.f;

    const float* Ap = A + (size_t)(m0 + lr) * K + lk;
    const int brow = n0 + lr;
    const float* Bp = B + (size_t)brow * K + lk;
    const bool bv = brow < N;

    for (int kt = 0; kt < K; kt += 16) {
        float4 a = *(const float4*)(Ap + kt);
        float4 b = bv ? *(const float4*)(Bp + kt) : make_float4(0.f, 0.f, 0.f, 0.f);
        __syncthreads();
        As[(lk + 0) * 68 + lr] = a.x;
        As[(lk + 1) * 68 + lr] = a.y;
        As[(lk + 2) * 68 + lr] = a.z;
        As[(lk + 3) * 68 + lr] = a.w;
        Bs[(lk + 0) * 68 + lr] = b.x;
        Bs[(lk + 1) * 68 + lr] = b.y;
        Bs[(lk + 2) * 68 + lr] = b.z;
        Bs[(lk + 3) * 68 + lr] = b.w;
        __syncthreads();
#pragma unroll
        for (int kk = 0; kk < 16; kk++) {
            float4 av = *(const float4*)&As[kk * 68 + ty * 4];
            float4 bv4 = *(const float4*)&Bs[kk * 68 + tx * 4];
            float ar[4] = {av.x, av.y, av.z, av.w};
            float br[4] = {bv4.x, bv4.y, bv4.z, bv4.w};
#pragma unroll
            for (int i = 0; i < 4; i++)
#pragma unroll
                for (int j = 0; j < 4; j++) acc[i][j] = fmaf(ar[i], br[j], acc[i][j]);
        }
    }

#pragma unroll
    for (int i = 0; i < 4; i++) {
        int row = m0 + ty * 4 + i;
        int col0 = n0 + tx * 4;
        if (col0 + 3 < N) {
            float4 o = make_float4(acc[i][0], acc[i][1], acc[i][2], acc[i][3]);
            *(float4*)&C[(size_t)row * N + col0] = o;
        } else {
#pragma unroll
            for (int j = 0; j < 4; j++)
                if (col0 + j < N) C[(size_t)row * N + col0 + j] = acc[i][j];
        }
    }
}

__global__ void __launch_bounds__(256) gemm_gate(const float* __restrict__ X,
                                                 const float* __restrict__ Wg) {
    gemm_nt_body(X, Wg, g_gate, 36, D);
}

// ---------------- cumsum of u over L, per channel ---------------------------
__global__ void cumsum_u() {
    int c = blockIdx.x * blockDim.x + threadIdx.x;
    if (c >= D) return;
    float acc = 0.f;
#pragma unroll 8
    for (int l = 0; l < L; l++) {
        acc += g_u[l * D + c];
        g_usum[l * D + c] = acc;
    }
}

// ---------------- s_i = -(1/sqrt(d)) * u . bar_u ----------------------------
__global__ void compute_s(const float* __restrict__ pmu,
                          const float* __restrict__ plt) {
    int gw = (blockIdx.x * blockDim.x + threadIdx.x) >> 5;
    int lane = threadIdx.x & 31;
    if (gw >= LH) return;
    int l = gw / NH, h = gw % NH;
    float lt = expf(fminf(fmaxf(plt[h], -50.f), 30.f));
    float t = (float)(l + 1);
    float inv_den = 1.f / (lt + t);
    float acc = 0.f;
#pragma unroll
    for (int r = 0; r < 2; r++) {
        int i = lane + r * 32;
        float uu = g_u[l * D + h * HD + i];
        float bu = (lt * pmu[h * HD + i] + g_usum[l * D + h * HD + i]) * inv_den;
        acc = fmaf(uu, bu, acc);
    }
#pragma unroll
    for (int o = 16; o; o >>= 1) acc += __shfl_xor_sync(0xffffffffu, acc, o);
    if (lane == 0) g_s[l * NH + h] = -acc * 0.125f;
}

// ---------------- per-head: max, scans, gate coefficients -------------------
__global__ void __launch_bounds__(1024) head_scan() {
    __shared__ float she[1024];
    __shared__ float shp[1024];
    const int h = blockIdx.x;
    const int l = threadIdx.x;
    float s = g_s[l * NH + h];
    she[l] = s;
    __syncthreads();
    for (int off = 512; off > 0; off >>= 1) {
        if (l < off) she[l] = fmaxf(she[l], she[l + off]);
        __syncthreads();
    }
    float smax = she[0];
    __syncthreads();
    float e = expf(s - smax);
    float ev = e, pv = s;
    she[l] = ev;
    shp[l] = pv;
    __syncthreads();
    for (int off = 1; off < 1024; off <<= 1) {
        float ae = 0.f, ap = 0.f;
        if (l >= off) { ae = she[l - off]; ap = shp[l - off]; }
        __syncthreads();
        ev += ae;
        pv += ap;
        she[l] = ev;
        shp[l] = pv;
        __syncthreads();
    }
    float g1 = g_gate[l * 36 + h * 3 + 0];
    float gh = g_gate[l * 36 + h * 3 + 1];
    float s1 = 1.f / (1.f + expf(-g1));
    float shg = 1.f / (1.f + expf(-gh));
    float t = (float)(l + 1);
    float a = shg / (ev + 1e-12f);
    float b = (s1 - shg) / t;
    float gm = -(b * pv + shg) / t;
    int o = l * NH + h;
    g_es[o] = e;
    g_al[o] = a;
    g_be[o] = b;
    g_ga[o] = gm;
}

// ---------------- RoPE + L2 normalize on q, k (fp32, matches reference) -----
__global__ void rope_norm() {
    int gw = (blockIdx.x * blockDim.x + threadIdx.x) >> 5;
    int lane = threadIdx.x & 31;
    if (gw >= LH) return;
    int l = gw / NH, h = gw % NH;
    int base = l * D + h * HD;
    int i0 = lane >> 1;
    const float LN1E4_32 = 0.28782313662425572f;  // ln(10000)/32
    float f0 = expf(-(float)i0 * LN1E4_32);
    float f1 = expf(-(float)(i0 + 16) * LN1E4_32);
    float a0 = (float)l * f0;
    float a1 = (float)l * f1;
    float c0 = cosf(a0), sn0 = sinf(a0);
    float c1 = cosf(a1), sn1 = sinf(a1);

    {
        float x0 = g_q[base + lane], x1 = g_q[base + lane + 32];
        float r0 = x0 * c0 - x1 * sn0;
        float r1 = x1 * c1 + x0 * sn1;
        float nn = r0 * r0 + r1 * r1;
#pragma unroll
        for (int o = 16; o; o >>= 1) nn += __shfl_xor_sync(0xffffffffu, nn, o);
        float inv = 1.f / fmaxf(sqrtf(nn), 1e-12f);
        g_q[base + lane] = r0 * inv;
        g_q[base + lane + 32] = r1 * inv;
    }
    {
        float x0 = g_k[base + lane], x1 = g_k[base + lane + 32];
        float r0 = x0 * c0 - x1 * sn0;
        float r1 = x1 * c1 + x0 * sn1;
        float nn = r0 * r0 + r1 * r1;
#pragma unroll
        for (int o = 16; o; o >>= 1) nn += __shfl_xor_sync(0xffffffffu, nn, o);
        float inv = 1.f / fmaxf(sqrtf(nn), 1e-12f);
        g_k[base + lane] = r0 * inv;
        g_k[base + lane + 32] = r1 * inv;
    }
}

// ---------------- weighted causal attention + fused LayerNorm ---------------
// out_l = sum_{j<=l} (q_l.k_j) * (al_l*es_j + be_l*s_j + ga_l) * v_j
#define ATTN_SMEM ((2 * 64 * 68 + 64 * 64) * 4)

__global__ void __launch_bounds__(256) attn_kernel() {
    extern __shared__ float smem[];
    float* Qs = smem;                 // [d][m], stride 68
    float* KSs = smem + 64 * 68;      // [d][j] then reused as S^T [j][m]
    float* Vs = smem + 2 * 64 * 68;   // [j][e], stride 64
    __shared__ float cA[64], cB[64], cG[64], sES[64], sS[64];

    const int h = blockIdx.y;
    const int lt = 15 - blockIdx.x;
    const int l0 = lt * 64;
    const int tid = threadIdx.x;
    const int tx = tid & 15, ty = tid >> 4;

#pragma unroll
    for (int it = 0; it < 4; it++) {
        int idx = tid + it * 256;
        int row = idx >> 4;
        int c4 = (idx & 15) << 2;
        float4 x = *(const float4*)(g_q + (l0 + row) * D + h * HD + c4);
        Qs[(c4 + 0) * 68 + row] = x.x;
        Qs[(c4 + 1) * 68 + row] = x.y;
        Qs[(c4 + 2) * 68 + row] = x.z;
        Qs[(c4 + 3) * 68 + row] = x.w;
    }
    if (tid < 64) {
        cA[tid] = g_al[(l0 + tid) * NH + h];
        cB[tid] = g_be[(l0 + tid) * NH + h];
        cG[tid] = g_ga[(l0 + tid) * NH + h];
    }

    float oacc[4][4];
#pragma unroll
    for (int i = 0; i < 4; i++)
#pragma unroll
        for (int j = 0; j < 4; j++) oacc[i][j] = 0.f;

    for (int jt = 0; jt <= lt; jt++) {
        const int j0 = jt * 64;
        __syncthreads();
#pragma unroll
        for (int it = 0; it < 4; it++) {
            int idx = tid + it * 256;
            int row = idx >> 4;
            int c4 = (idx & 15) << 2;
            float4 xk = *(const float4*)(g_k + (j0 + row) * D + h * HD + c4);
            KSs[(c4 + 0) * 68 + row] = xk.x;
            KSs[(c4 + 1) * 68 + row] = xk.y;
            KSs[(c4 + 2) * 68 + row] = xk.z;
            KSs[(c4 + 3) * 68 + row] = xk.w;
            float4 xv = *(const float4*)(g_v + (j0 + row) * D + h * HD + c4);
            *(float4*)&Vs[row * 64 + c4] = xv;
        }
        if (tid < 64) {
            sES[tid] = g_es[(j0 + tid) * NH + h];
            sS[tid] = g_s[(j0 + tid) * NH + h];
        }
        __syncthreads();

        float sacc[4][4];
#pragma unroll
        for (int i = 0; i < 4; i++)
#pragma unroll
            for (int j = 0; j < 4; j++) sacc[i][j] = 0.f;
#pragma unroll 8
        for (int kk = 0; kk < 64; kk++) {
            float4 av = *(const float4*)&Qs[kk * 68 + ty * 4];
            float4 bv = *(const float4*)&KSs[kk * 68 + tx * 4];
            float ar[4] = {av.x, av.y, av.z, av.w};
            float br[4] = {bv.x, bv.y, bv.z, bv.w};
#pragma unroll
            for (int i = 0; i < 4; i++)
#pragma unroll
                for (int j = 0; j < 4; j++) sacc[i][j] = fmaf(ar[i], br[j], sacc[i][j]);
        }
        __syncthreads();

#pragma unroll
        for (int i = 0; i < 4; i++) {
            int r = ty * 4 + i;
            int gl = l0 + r;
            float Ar = cA[r], Br = cB[r], Gr = cG[r];
#pragma unroll
            for (int j = 0; j < 4; j++) {
                int c = tx * 4 + j;
                int gj = j0 + c;
                float w = Ar * sES[c] + Br * sS[c] + Gr;
                KSs[c * 68 + r] = (gj <= gl) ? sacc[i][j] * w : 0.f;
            }
        }
        __syncthreads();

#pragma unroll 8
        for (int c = 0; c < 64; c++) {
            float4 av = *(const float4*)&KSs[c * 68 + ty * 4];
            float4 bv = *(const float4*)&Vs[c * 64 + tx * 4];
            float ar[4] = {av.x, av.y, av.z, av.w};
            float br[4] = {bv.x, bv.y, bv.z, bv.w};
#pragma unroll
            for (int i = 0; i < 4; i++)
#pragma unroll
                for (int j = 0; j < 4; j++) oacc[i][j] = fmaf(ar[i], br[j], oacc[i][j]);
        }
    }

    // fused LayerNorm, emit split-bf16 for the Wo GEMM
#pragma unroll
    for (int i = 0; i < 4; i++) {
        float sum = oacc[i][0] + oacc[i][1] + oacc[i][2] + oacc[i][3];
#pragma unroll
        for (int o = 8; o; o >>= 1) sum += __shfl_xor_sync(0xffffffffu, sum, o);
        float mean = sum * (1.f / 64.f);
        float d0 = oacc[i][0] - mean, d1 = oacc[i][1] - mean;
        float d2 = oacc[i][2] - mean, d3 = oacc[i][3] - mean;
        float vs = d0 * d0 + d1 * d1 + d2 * d2 + d3 * d3;
#pragma unroll
        for (int o = 8; o; o >>= 1) vs += __shfl_xor_sync(0xffffffffu, vs, o);
        float inv = rsqrtf(vs * (1.f / 64.f) + 1e-5f);
        float v0 = d0 * inv, v1 = d1 * inv, v2 = d2 * inv, v3 = d3 * inv;

        int off = (l0 + ty * 4 + i) * D + h * HD + tx * 4;
        __nv_bfloat16 h0 = __float2bfloat16(v0);
        __nv_bfloat16 h1 = __float2bfloat16(v1);
        __nv_bfloat16 h2 = __float2bfloat16(v2);
        __nv_bfloat16 h3 = __float2bfloat16(v3);
        __nv_bfloat162 hp0 = __nv_bfloat162(h0, h1);
        __nv_bfloat162 hp1 = __nv_bfloat162(h2, h3);
        *(__nv_bfloat162*)&g_lnh[off] = hp0;
        *(__nv_bfloat162*)&g_lnh[off + 2] = hp1;
        __nv_bfloat162 lp0 = __nv_bfloat162(
            __float2bfloat16(v0 - __bfloat162float(h0)),
            __float2bfloat16(v1 - __bfloat162float(h1)));
        __nv_bfloat162 lp1 = __nv_bfloat162(
            __float2bfloat16(v2 - __bfloat162float(h2)),
            __float2bfloat16(v3 - __bfloat162float(h3)));
        *(__nv_bfloat162*)&g_lnl[off] = lp0;
        *(__nv_bfloat162*)&g_lnl[off + 2] = lp1;
    }
}

// ---------------- launch ----------------------------------------------------
extern "C" void kernel_launch(void* const* d_in, const int* in_sizes, int n_in,
                              void* d_out, int out_size) {
    const float* X = (const float*)d_in[0];
    const float* Wq = (const float*)d_in[1];
    const float* Wk = (const float*)d_in[2];
    const float* Wv = (const float*)d_in[3];
    const float* Wu = (const float*)d_in[4];
    const float* Wg = (const float*)d_in[5];
    const float* Wo = (const float*)d_in[6];
    const float* pmu = (const float*)d_in[7];
    const float* plt = (const float*)d_in[8];
    float* out = (float*)d_out;

    cudaFuncSetAttribute(attn_kernel, cudaFuncAttributeMaxDynamicSharedMemorySize,
                         ATTN_SMEM);

    // split-bf16 conversion of X and weights
    convert_inputs<<<dim3(96, 6), 256>>>(X, Wq, Wk, Wv, Wu, Wo);

    // projections on tensor cores
    gemm_qkvu_tc<<<dim3(D / BN, L / BM, 4), 256>>>();
    gemm_gate<<<dim3(1, L / 64), 256>>>(X, Wg);

    // logits pipeline
    cumsum_u<<<(D + 127) / 128, 128>>>();
    compute_s<<<(LH * 32 + 255) / 256, 256>>>(pmu, plt);
    head_scan<<<NH, 1024>>>();

    // RoPE + normalize
    rope_norm<<<(LH * 32 + 255) / 256, 256>>>();

    // attention + fused LayerNorm (emits split-bf16)
    attn_kernel<<<dim3(16, NH), 256, ATTN_SMEM>>>();

    // output projection on tensor cores
    gemm_out_tc<<<dim3(D / BN, L / BM), 256>>>(out);
}

// round 3
// speedup vs baseline: 2.1465x; 1.6953x over previous
#include <cuda_runtime.h>
#include <cuda_bf16.h>
#include <mma.h>
#include <math.h>

using namespace nvcuda;

#define L 1024
#define D 768
#define NH 12
#define HD 64
#define LH (L*NH)

// ---------------- scratch (device globals; no allocation allowed) ----------
__device__ float g_q[L*D];
__device__ float g_k[L*D];
__device__ float g_v[L*D];
__device__ float g_u[L*D];
__device__ float g_usum[L*D];
__device__ float g_gate[L*36];
__device__ float g_s[LH];
__device__ float g_es[LH];
__device__ float g_al[LH];
__device__ float g_be[LH];
__device__ float g_ga[LH];

// split-bf16 buffers
__device__ __nv_bfloat16 g_Xh[L*D];
__device__ __nv_bfloat16 g_Xl[L*D];
__device__ __nv_bfloat16 g_Wh[5*D*D];   // Wq,Wk,Wv,Wu,Wo
__device__ __nv_bfloat16 g_Wl[5*D*D];
__device__ __nv_bfloat16 g_lnh[L*D];
__device__ __nv_bfloat16 g_lnl[L*D];

// ---------------- fp32 -> (hi, lo) bf16 conversion --------------------------
__global__ void convert_inputs(const float* __restrict__ X,
                               const float* __restrict__ Wq,
                               const float* __restrict__ Wk,
                               const float* __restrict__ Wv,
                               const float* __restrict__ Wu,
                               const float* __restrict__ Wo) {
    int z = blockIdx.y;
    const float* src;
    __nv_bfloat16 *dh, *dl;
    int n;
    if (z == 0) { src = X; dh = g_Xh; dl = g_Xl; n = L * D; }
    else {
        const float* ws[5] = {Wq, Wk, Wv, Wu, Wo};
        src = ws[z - 1];
        dh = g_Wh + (z - 1) * D * D;
        dl = g_Wl + (z - 1) * D * D;
        n = D * D;
    }
    for (int i = blockIdx.x * blockDim.x + threadIdx.x; i < n;
         i += gridDim.x * blockDim.x) {
        float v = src[i];
        __nv_bfloat16 h = __float2bfloat16(v);
        dh[i] = h;
        dl[i] = __float2bfloat16(v - __bfloat162float(h));
    }
}

// ---------------- split-bf16 tensor-core GEMM -------------------------------
// C[1024,768] = A[1024,768] * B[768,768]^T via 3 passes:
//   Ah*Bh + Al*Bh + Ah*Bl   (drops Al*Bl ~ 2^-16 rel)
#define BM 128
#define BN 64
#define BK 64
#define LDS_ 72

__device__ __forceinline__ void gemm_bf16_body(
    const __nv_bfloat16* __restrict__ Ah, const __nv_bfloat16* __restrict__ Al,
    const __nv_bfloat16* __restrict__ Bh, const __nv_bfloat16* __restrict__ Bl,
    float* __restrict__ C) {
    __shared__ __nv_bfloat16 As[BM * LDS_];
    __shared__ __nv_bfloat16 Bs[BN * LDS_];
    const int tid = threadIdx.x;
    const int warp = tid >> 5;
    const int wm = warp >> 1, wn = warp & 1;
    const int m0 = blockIdx.y * BM, n0 = blockIdx.x * BN;

    wmma::fragment<wmma::accumulator, 16, 16, 16, float> acc[2][2];
#pragma unroll
    for (int i = 0; i < 2; i++)
#pragma unroll
        for (int j = 0; j < 2; j++) wmma::fill_fragment(acc[i][j], 0.f);

#pragma unroll 1
    for (int seg = 0; seg < 3; seg++) {
        const __nv_bfloat16* A = (seg == 1) ? Al : Ah;
        const __nv_bfloat16* B = (seg == 2) ? Bl : Bh;
#pragma unroll 1
        for (int kt = 0; kt < D; kt += BK) {
            __syncthreads();
#pragma unroll
            for (int i = 0; i < 4; i++) {
                int idx = tid + i * 256;
                int r = idx >> 3;
                int c = (idx & 7) * 8;
                *(uint4*)&As[r * LDS_ + c] =
                    *(const uint4*)&A[(size_t)(m0 + r) * D + kt + c];
            }
#pragma unroll
            for (int i = 0; i < 2; i++) {
                int idx = tid + i * 256;
                int r = idx >> 3;
                int c = (idx & 7) * 8;
                *(uint4*)&Bs[r * LDS_ + c] =
                    *(const uint4*)&B[(size_t)(n0 + r) * D + kt + c];
            }
            __syncthreads();
#pragma unroll
            for (int kk = 0; kk < BK; kk += 16) {
                wmma::fragment<wmma::matrix_a, 16, 16, 16, __nv_bfloat16,
                               wmma::row_major> a0, a1;
                wmma::fragment<wmma::matrix_b, 16, 16, 16, __nv_bfloat16,
                               wmma::col_major> b0, b1;
                wmma::load_matrix_sync(a0, &As[(wm * 32) * LDS_ + kk], LDS_);
                wmma::load_matrix_sync(a1, &As[(wm * 32 + 16) * LDS_ + kk], LDS_);
                wmma::load_matrix_sync(b0, &Bs[(wn * 32) * LDS_ + kk], LDS_);
                wmma::load_matrix_sync(b1, &Bs[(wn * 32 + 16) * LDS_ + kk], LDS_);
                wmma::mma_sync(acc[0][0], a0, b0, acc[0][0]);
                wmma::mma_sync(acc[0][1], a0, b1, acc[0][1]);
                wmma::mma_sync(acc[1][0], a1, b0, acc[1][0]);
                wmma::mma_sync(acc[1][1], a1, b1, acc[1][1]);
            }
        }
    }

#pragma unroll
    for (int i = 0; i < 2; i++)
#pragma unroll
        for (int j = 0; j < 2; j++)
            wmma::store_matrix_sync(
                &C[(size_t)(m0 + wm * 32 + i * 16) * D + n0 + wn * 32 + j * 16],
                acc[i][j], D, wmma::mem_row_major);
}

__global__ void __launch_bounds__(256) gemm_qkvu_tc() {
    int z = blockIdx.z;
    float* Cs[4] = {g_q, g_k, g_v, g_u};
    gemm_bf16_body(g_Xh, g_Xl, g_Wh + (size_t)z * D * D, g_Wl + (size_t)z * D * D,
                   Cs[z]);
}

__global__ void __launch_bounds__(256) gemm_out_tc(float* __restrict__ out) {
    gemm_bf16_body(g_lnh, g_lnl, g_Wh + (size_t)4 * D * D,
                   g_Wl + (size_t)4 * D * D, out);
}

// ---------------- fp32 NT GEMM (kept for small gate matmul) -----------------
__device__ __forceinline__ void gemm_nt_body(const float* __restrict__ A,
                                             const float* __restrict__ B,
                                             float* __restrict__ C,
                                             int N, int K) {
    __shared__ float As[16 * 68];
    __shared__ float Bs[16 * 68];
    const int tid = threadIdx.x;
    const int tx = tid & 15, ty = tid >> 4;
    const int m0 = blockIdx.y * 64, n0 = blockIdx.x * 64;
    const int lr = tid >> 2;
    const int lk = (tid & 3) * 4;

    float acc[4][4];
#pragma unroll
    for (int i = 0; i < 4; i++)
#pragma unroll
        for (int j = 0; j < 4; j++) acc[i][j] = 0.f;

    const float* Ap = A + (size_t)(m0 + lr) * K + lk;
    const int brow = n0 + lr;
    const float* Bp = B + (size_t)brow * K + lk;
    const bool bv = brow < N;

    for (int kt = 0; kt < K; kt += 16) {
        float4 a = *(const float4*)(Ap + kt);
        float4 b = bv ? *(const float4*)(Bp + kt) : make_float4(0.f, 0.f, 0.f, 0.f);
        __syncthreads();
        As[(lk + 0) * 68 + lr] = a.x;
        As[(lk + 1) * 68 + lr] = a.y;
        As[(lk + 2) * 68 + lr] = a.z;
        As[(lk + 3) * 68 + lr] = a.w;
        Bs[(lk + 0) * 68 + lr] = b.x;
        Bs[(lk + 1) * 68 + lr] = b.y;
        Bs[(lk + 2) * 68 + lr] = b.z;
        Bs[(lk + 3) * 68 + lr] = b.w;
        __syncthreads();
#pragma unroll
        for (int kk = 0; kk < 16; kk++) {
            float4 av = *(const float4*)&As[kk * 68 + ty * 4];
            float4 bv4 = *(const float4*)&Bs[kk * 68 + tx * 4];
            float ar[4] = {av.x, av.y, av.z, av.w};
            float br[4] = {bv4.x, bv4.y, bv4.z, bv4.w};
#pragma unroll
            for (int i = 0; i < 4; i++)
#pragma unroll
                for (int j = 0; j < 4; j++) acc[i][j] = fmaf(ar[i], br[j], acc[i][j]);
        }
    }

#pragma unroll
    for (int i = 0; i < 4; i++) {
        int row = m0 + ty * 4 + i;
        int col0 = n0 + tx * 4;
        if (col0 + 3 < N) {
            float4 o = make_float4(acc[i][0], acc[i][1], acc[i][2], acc[i][3]);
            *(float4*)&C[(size_t)row * N + col0] = o;
        } else {
#pragma unroll
            for (int j = 0; j < 4; j++)
                if (col0 + j < N) C[(size_t)row * N + col0 + j] = acc[i][j];
        }
    }
}

__global__ void __launch_bounds__(256) gemm_gate(const float* __restrict__ X,
                                                 const float* __restrict__ Wg) {
    gemm_nt_body(X, Wg, g_gate, 36, D);
}

// ---------------- cumsum of u over L: warp-per-channel shuffle scan ---------
__global__ void __launch_bounds__(256) cumsum_u_fast() {
    const int c = blockIdx.x * 8 + (threadIdx.x >> 5);
    const int lane = threadIdx.x & 31;
    if (c >= D) return;
    float carry = 0.f;
#pragma unroll 1
    for (int l0 = 0; l0 < L; l0 += 32) {
        float v = g_u[(l0 + lane) * D + c];
#pragma unroll
        for (int o = 1; o < 32; o <<= 1) {
            float n = __shfl_up_sync(0xffffffffu, v, o);
            if (lane >= o) v += n;
        }
        v += carry;
        g_usum[(l0 + lane) * D + c] = v;
        carry = __shfl_sync(0xffffffffu, v, 31);
    }
}

// ---------------- s_i = -(1/sqrt(d)) * u . bar_u ----------------------------
__global__ void compute_s(const float* __restrict__ pmu,
                          const float* __restrict__ plt) {
    int gw = (blockIdx.x * blockDim.x + threadIdx.x) >> 5;
    int lane = threadIdx.x & 31;
    if (gw >= LH) return;
    int l = gw / NH, h = gw % NH;
    float lt = expf(fminf(fmaxf(plt[h], -50.f), 30.f));
    float t = (float)(l + 1);
    float inv_den = 1.f / (lt + t);
    float acc = 0.f;
#pragma unroll
    for (int r = 0; r < 2; r++) {
        int i = lane + r * 32;
        float uu = g_u[l * D + h * HD + i];
        float bu = (lt * pmu[h * HD + i] + g_usum[l * D + h * HD + i]) * inv_den;
        acc = fmaf(uu, bu, acc);
    }
#pragma unroll
    for (int o = 16; o; o >>= 1) acc += __shfl_xor_sync(0xffffffffu, acc, o);
    if (lane == 0) g_s[l * NH + h] = -acc * 0.125f;
}

// ---------------- per-head: max, scans, gate coefficients -------------------
__global__ void __launch_bounds__(1024) head_scan() {
    __shared__ float she[1024];
    __shared__ float shp[1024];
    const int h = blockIdx.x;
    const int l = threadIdx.x;
    float s = g_s[l * NH + h];
    she[l] = s;
    __syncthreads();
    for (int off = 512; off > 0; off >>= 1) {
        if (l < off) she[l] = fmaxf(she[l], she[l + off]);
        __syncthreads();
    }
    float smax = she[0];
    __syncthreads();
    float e = expf(s - smax);
    float ev = e, pv = s;
    she[l] = ev;
    shp[l] = pv;
    __syncthreads();
    for (int off = 1; off < 1024; off <<= 1) {
        float ae = 0.f, ap = 0.f;
        if (l >= off) { ae = she[l - off]; ap = shp[l - off]; }
        __syncthreads();
        ev += ae;
        pv += ap;
        she[l] = ev;
        shp[l] = pv;
        __syncthreads();
    }
    float g1 = g_gate[l * 36 + h * 3 + 0];
    float gh = g_gate[l * 36 + h * 3 + 1];
    float s1 = 1.f / (1.f + expf(-g1));
    float shg = 1.f / (1.f + expf(-gh));
    float t = (float)(l + 1);
    float a = shg / (ev + 1e-12f);
    float b = (s1 - shg) / t;
    float gm = -(b * pv + shg) / t;
    int o = l * NH + h;
    g_es[o] = e;
    g_al[o] = a;
    g_be[o] = b;
    g_ga[o] = gm;
}

// ---------------- RoPE + L2 normalize on q, k (fp32) ------------------------
__global__ void rope_norm() {
    int gw = (blockIdx.x * blockDim.x + threadIdx.x) >> 5;
    int lane = threadIdx.x & 31;
    if (gw >= LH) return;
    int l = gw / NH, h = gw % NH;
    int base = l * D + h * HD;
    int i0 = lane >> 1;
    const float LN1E4_32 = 0.28782313662425572f;  // ln(10000)/32
    float f0 = expf(-(float)i0 * LN1E4_32);
    float f1 = expf(-(float)(i0 + 16) * LN1E4_32);
    float a0 = (float)l * f0;
    float a1 = (float)l * f1;
    float c0 = cosf(a0), sn0 = sinf(a0);
    float c1 = cosf(a1), sn1 = sinf(a1);

    {
        float x0 = g_q[base + lane], x1 = g_q[base + lane + 32];
        float r0 = x0 * c0 - x1 * sn0;
        float r1 = x1 * c1 + x0 * sn1;
        float nn = r0 * r0 + r1 * r1;
#pragma unroll
        for (int o = 16; o; o >>= 1) nn += __shfl_xor_sync(0xffffffffu, nn, o);
        float inv = 1.f / fmaxf(sqrtf(nn), 1e-12f);
        g_q[base + lane] = r0 * inv;
        g_q[base + lane + 32] = r1 * inv;
    }
    {
        float x0 = g_k[base + lane], x1 = g_k[base + lane + 32];
        float r0 = x0 * c0 - x1 * sn0;
        float r1 = x1 * c1 + x0 * sn1;
        float nn = r0 * r0 + r1 * r1;
#pragma unroll
        for (int o = 16; o; o >>= 1) nn += __shfl_xor_sync(0xffffffffu, nn, o);
        float inv = 1.f / fmaxf(sqrtf(nn), 1e-12f);
        g_k[base + lane] = r0 * inv;
        g_k[base + lane + 32] = r1 * inv;
    }
}

// ---------------- weighted causal attention + fused LayerNorm ---------------
// out_l = sum_{j<=l} (q_l.k_j) * (al_l*es_j + be_l*s_j + ga_l) * v_j
#define ATTN_SMEM ((2 * 64 * 68 + 64 * 64) * 4)

__global__ void __launch_bounds__(256) attn_kernel() {
    extern __shared__ float smem[];
    float* Qs = smem;                 // [d][m], stride 68
    float* KSs = smem + 64 * 68;      // [d][j] then reused as S^T [j][m]
    float* Vs = smem + 2 * 64 * 68;   // [j][e], stride 64
    __shared__ float cA[64], cB[64], cG[64], sES[64], sS[64];

    const int h = blockIdx.y;
    const int lt = 15 - blockIdx.x;
    const int l0 = lt * 64;
    const int tid = threadIdx.x;
    const int tx = tid & 15, ty = tid >> 4;

#pragma unroll
    for (int it = 0; it < 4; it++) {
        int idx = tid + it * 256;
        int row = idx >> 4;
        int c4 = (idx & 15) << 2;
        float4 x = *(const float4*)(g_q + (l0 + row) * D + h * HD + c4);
        Qs[(c4 + 0) * 68 + row] = x.x;
        Qs[(c4 + 1) * 68 + row] = x.y;
        Qs[(c4 + 2) * 68 + row] = x.z;
        Qs[(c4 + 3) * 68 + row] = x.w;
    }
    if (tid < 64) {
        cA[tid] = g_al[(l0 + tid) * NH + h];
        cB[tid] = g_be[(l0 + tid) * NH + h];
        cG[tid] = g_ga[(l0 + tid) * NH + h];
    }

    float oacc[4][4];
#pragma unroll
    for (int i = 0; i < 4; i++)
#pragma unroll
        for (int j = 0; j < 4; j++) oacc[i][j] = 0.f;

    for (int jt = 0; jt <= lt; jt++) {
        const int j0 = jt * 64;
        __syncthreads();
#pragma unroll
        for (int it = 0; it < 4; it++) {
            int idx = tid + it * 256;
            int row = idx >> 4;
            int c4 = (idx & 15) << 2;
            float4 xk = *(const float4*)(g_k + (j0 + row) * D + h * HD + c4);
            KSs[(c4 + 0) * 68 + row] = xk.x;
            KSs[(c4 + 1) * 68 + row] = xk.y;
            KSs[(c4 + 2) * 68 + row] = xk.z;
            KSs[(c4 + 3) * 68 + row] = xk.w;
            float4 xv = *(const float4*)(g_v + (j0 + row) * D + h * HD + c4);
            *(float4*)&Vs[row * 64 + c4] = xv;
        }
        if (tid < 64) {
            sES[tid] = g_es[(j0 + tid) * NH + h];
            sS[tid] = g_s[(j0 + tid) * NH + h];
        }
        __syncthreads();

        float sacc[4][4];
#pragma unroll
        for (int i = 0; i < 4; i++)
#pragma unroll
            for (int j = 0; j < 4; j++) sacc[i][j] = 0.f;
#pragma unroll 8
        for (int kk = 0; kk < 64; kk++) {
            float4 av = *(const float4*)&Qs[kk * 68 + ty * 4];
            float4 bv = *(const float4*)&KSs[kk * 68 + tx * 4];
            float ar[4] = {av.x, av.y, av.z, av.w};
            float br[4] = {bv.x, bv.y, bv.z, bv.w};
#pragma unroll
            for (int i = 0; i < 4; i++)
#pragma unroll
                for (int j = 0; j < 4; j++) sacc[i][j] = fmaf(ar[i], br[j], sacc[i][j]);
        }
        __syncthreads();

#pragma unroll
        for (int i = 0; i < 4; i++) {
            int r = ty * 4 + i;
            int gl = l0 + r;
            float Ar = cA[r], Br = cB[r], Gr = cG[r];
#pragma unroll
            for (int j = 0; j < 4; j++) {
                int c = tx * 4 + j;
                int gj = j0 + c;
                float w = Ar * sES[c] + Br * sS[c] + Gr;
                KSs[c * 68 + r] = (gj <= gl) ? sacc[i][j] * w : 0.f;
            }
        }
        __syncthreads();

#pragma unroll 8
        for (int c = 0; c < 64; c++) {
            float4 av = *(const float4*)&KSs[c * 68 + ty * 4];
            float4 bv = *(const float4*)&Vs[c * 64 + tx * 4];
            float ar[4] = {av.x, av.y, av.z, av.w};
            float br[4] = {bv.x, bv.y, bv.z, bv.w};
#pragma unroll
            for (int i = 0; i < 4; i++)
#pragma unroll
                for (int j = 0; j < 4; j++) oacc[i][j] = fmaf(ar[i], br[j], oacc[i][j]);
        }
    }

    // fused LayerNorm, emit split-bf16 for the Wo GEMM
#pragma unroll
    for (int i = 0; i < 4; i++) {
        float sum = oacc[i][0] + oacc[i][1] + oacc[i][2] + oacc[i][3];
#pragma unroll
        for (int o = 8; o; o >>= 1) sum += __shfl_xor_sync(0xffffffffu, sum, o);
        float mean = sum * (1.f / 64.f);
        float d0 = oacc[i][0] - mean, d1 = oacc[i][1] - mean;
        float d2 = oacc[i][2] - mean, d3 = oacc[i][3] - mean;
        float vs = d0 * d0 + d1 * d1 + d2 * d2 + d3 * d3;
#pragma unroll
        for (int o = 8; o; o >>= 1) vs += __shfl_xor_sync(0xffffffffu, vs, o);
        float inv = rsqrtf(vs * (1.f / 64.f) + 1e-5f);
        float v0 = d0 * inv, v1 = d1 * inv, v2 = d2 * inv, v3 = d3 * inv;

        int off = (l0 + ty * 4 + i) * D + h * HD + tx * 4;
        __nv_bfloat16 h0 = __float2bfloat16(v0);
        __nv_bfloat16 h1 = __float2bfloat16(v1);
        __nv_bfloat16 h2 = __float2bfloat16(v2);
        __nv_bfloat16 h3 = __float2bfloat16(v3);
        __nv_bfloat162 hp0 = __nv_bfloat162(h0, h1);
        __nv_bfloat162 hp1 = __nv_bfloat162(h2, h3);
        *(__nv_bfloat162*)&g_lnh[off] = hp0;
        *(__nv_bfloat162*)&g_lnh[off + 2] = hp1;
        __nv_bfloat162 lp0 = __nv_bfloat162(
            __float2bfloat16(v0 - __bfloat162float(h0)),
            __float2bfloat16(v1 - __bfloat162float(h1)));
        __nv_bfloat162 lp1 = __nv_bfloat162(
            __float2bfloat16(v2 - __bfloat162float(h2)),
            __float2bfloat16(v3 - __bfloat162float(h3)));
        *(__nv_bfloat162*)&g_lnl[off] = lp0;
        *(__nv_bfloat162*)&g_lnl[off + 2] = lp1;
    }
}

// ---------------- launch ----------------------------------------------------
extern "C" void kernel_launch(void* const* d_in, const int* in_sizes, int n_in,
                              void* d_out, int out_size) {
    const float* X = (const float*)d_in[0];
    const float* Wq = (const float*)d_in[1];
    const float* Wk = (const float*)d_in[2];
    const float* Wv = (const float*)d_in[3];
    const float* Wu = (const float*)d_in[4];
    const float* Wg = (const float*)d_in[5];
    const float* Wo = (const float*)d_in[6];
    const float* pmu = (const float*)d_in[7];
    const float* plt = (const float*)d_in[8];
    float* out = (float*)d_out;

    cudaFuncSetAttribute(attn_kernel, cudaFuncAttributeMaxDynamicSharedMemorySize,
                         ATTN_SMEM);

    // split-bf16 conversion of X and weights
    convert_inputs<<<dim3(96, 6), 256>>>(X, Wq, Wk, Wv, Wu, Wo);

    // projections on tensor cores
    gemm_qkvu_tc<<<dim3(D / BN, L / BM, 4), 256>>>();
    gemm_gate<<<dim3(1, L / 64), 256>>>(X, Wg);

    // logits pipeline (parallel warp-scan cumsum)
    cumsum_u_fast<<<D / 8, 256>>>();
    compute_s<<<(LH * 32 + 255) / 256, 256>>>(pmu, plt);
    head_scan<<<NH, 1024>>>();

    // RoPE + normalize
    rope_norm<<<(LH * 32 + 255) / 256, 256>>>();

    // attention + fused LayerNorm (emits split-bf16)
    attn_kernel<<<dim3(16, NH), 256, ATTN_SMEM>>>();

    // output projection on tensor cores
    gemm_out_tc<<<dim3(D / BN, L / BM), 256>>>(out);
}

// round 5
// speedup vs baseline: 2.2165x; 1.0326x over previous
#include <cuda_runtime.h>
#include <cuda_bf16.h>
#include <mma.h>
#include <math.h>
#include <cstdint>

using namespace nvcuda;

#define L 1024
#define D 768
#define NH 12
#define HD 64
#define LH (L*NH)

// ---------------- scratch (device globals; no allocation allowed) ----------
__device__ float g_q[L*D];
__device__ float g_k[L*D];
__device__ float g_v[L*D];
__device__ float g_u[L*D];
__device__ float g_usum[L*D];
__device__ float g_gate[L*36];
__device__ float g_s[LH];
__device__ float g_es[LH];
__device__ float g_al[LH];
__device__ float g_be[LH];
__device__ float g_ga[LH];

// split-bf16 buffers
__device__ __nv_bfloat16 g_Xh[L*D];
__device__ __nv_bfloat16 g_Xl[L*D];
__device__ __nv_bfloat16 g_Wh[5*D*D];   // Wq,Wk,Wv,Wu,Wo
__device__ __nv_bfloat16 g_Wl[5*D*D];
__device__ __nv_bfloat16 g_lnh[L*D];
__device__ __nv_bfloat16 g_lnl[L*D];

// ---------------- fp32 -> (hi, lo) bf16 conversion --------------------------
__global__ void convert_inputs(const float* __restrict__ X,
                               const float* __restrict__ Wq,
                               const float* __restrict__ Wk,
                               const float* __restrict__ Wv,
                               const float* __restrict__ Wu,
                               const float* __restrict__ Wo) {
    int z = blockIdx.y;
    const float* src;
    __nv_bfloat16 *dh, *dl;
    int n;
    if (z == 0) { src = X; dh = g_Xh; dl = g_Xl; n = L * D; }
    else {
        const float* ws[5] = {Wq, Wk, Wv, Wu, Wo};
        src = ws[z - 1];
        dh = g_Wh + (z - 1) * D * D;
        dl = g_Wl + (z - 1) * D * D;
        n = D * D;
    }
    for (int i = blockIdx.x * blockDim.x + threadIdx.x; i < n;
         i += gridDim.x * blockDim.x) {
        float v = src[i];
        __nv_bfloat16 h = __float2bfloat16(v);
        dh[i] = h;
        dl[i] = __float2bfloat16(v - __bfloat162float(h));
    }
}

// ---------------- cp.async helpers ------------------------------------------
__device__ __forceinline__ void cp16(void* dst, const void* src) {
    unsigned d = (unsigned)__cvta_generic_to_shared(dst);
    asm volatile("cp.async.cg.shared.global [%0], [%1], 16;" :: "r"(d), "l"(src));
}

// ---------------- split-bf16 tensor-core GEMM (double-buffered cp.async) ----
// C[*,768] tile = A[1024,768] * B[n0..n0+63,768]^T via 3 segment passes:
//   Ah*Bh + Al*Bh + Ah*Bl    flattened into a single 36-stage pipeline.
#define GBM 128
#define GBN 64
#define GBK 64
#define GLD 72
#define GEMM_SMEM ((GBM + GBN) * GLD * 2 * 2)   // 55296 bytes

__device__ __forceinline__ void gemm_stage_load(
    __nv_bfloat16* As, __nv_bfloat16* Bs,
    const __nv_bfloat16* __restrict__ A, const __nv_bfloat16* __restrict__ B,
    int m0, int n0, int kt, int tid) {
#pragma unroll
    for (int i = 0; i < 4; i++) {
        int idx = tid + i * 256;
        int r = idx >> 3, c8 = (idx & 7) * 8;
        cp16(&As[r * GLD + c8], &A[(size_t)(m0 + r) * D + kt + c8]);
    }
#pragma unroll
    for (int i = 0; i < 2; i++) {
        int idx = tid + i * 256;
        int r = idx >> 3, c8 = (idx & 7) * 8;
        cp16(&Bs[r * GLD + c8], &B[(size_t)(n0 + r) * D + kt + c8]);
    }
    asm volatile("cp.async.commit_group;");
}

__device__ __forceinline__ void gemm_body(
    const __nv_bfloat16* __restrict__ Ah, const __nv_bfloat16* __restrict__ Al,
    const __nv_bfloat16* __restrict__ Bh, const __nv_bfloat16* __restrict__ Bl,
    float* __restrict__ C, int m0, int n0) {
    extern __shared__ __nv_bfloat16 sh[];
    __nv_bfloat16* Asb[2] = {sh, sh + (GBM + GBN) * GLD};
    __nv_bfloat16* Bsb[2] = {sh + GBM * GLD, sh + (GBM + GBN) * GLD + GBM * GLD};

    const int tid = threadIdx.x;
    const int warp = tid >> 5;
    const int wm = warp >> 1, wn = warp & 1;

    wmma::fragment<wmma::accumulator, 16, 16, 16, float> acc[2][2];
#pragma unroll
    for (int i = 0; i < 2; i++)
#pragma unroll
        for (int j = 0; j < 2; j++) wmma::fill_fragment(acc[i][j], 0.f);

    const int NIT = 36;  // 3 segments x 12 k-tiles
    auto getAB = [&](int it, const __nv_bfloat16*& A, const __nv_bfloat16*& B,
                     int& kt) {
        int seg = it / 12;
        kt = (it % 12) * GBK;
        A = (seg == 1) ? Al : Ah;
        B = (seg == 2) ? Bl : Bh;
    };

    {
        const __nv_bfloat16 *A, *B;
        int kt;
        getAB(0, A, B, kt);
        gemm_stage_load(Asb[0], Bsb[0], A, B, m0, n0, kt, tid);
    }

#pragma unroll 1
    for (int it = 0; it < NIT; it++) {
        if (it + 1 < NIT) {
            const __nv_bfloat16 *A, *B;
            int kt;
            getAB(it + 1, A, B, kt);
            gemm_stage_load(Asb[(it + 1) & 1], Bsb[(it + 1) & 1], A, B, m0, n0,
                            kt, tid);
            asm volatile("cp.async.wait_group 1;");
        } else {
            asm volatile("cp.async.wait_group 0;");
        }
        __syncthreads();

        const __nv_bfloat16* As = Asb[it & 1];
        const __nv_bfloat16* Bs = Bsb[it & 1];
#pragma unroll
        for (int kk = 0; kk < GBK; kk += 16) {
            wmma::fragment<wmma::matrix_a, 16, 16, 16, __nv_bfloat16,
                           wmma::row_major> a0, a1;
            wmma::fragment<wmma::matrix_b, 16, 16, 16, __nv_bfloat16,
                           wmma::col_major> b0, b1;
            wmma::load_matrix_sync(a0, &As[(wm * 32) * GLD + kk], GLD);
            wmma::load_matrix_sync(a1, &As[(wm * 32 + 16) * GLD + kk], GLD);
            wmma::load_matrix_sync(b0, &Bs[(wn * 32) * GLD + kk], GLD);
            wmma::load_matrix_sync(b1, &Bs[(wn * 32 + 16) * GLD + kk], GLD);
            wmma::mma_sync(acc[0][0], a0, b0, acc[0][0]);
            wmma::mma_sync(acc[0][1], a0, b1, acc[0][1]);
            wmma::mma_sync(acc[1][0], a1, b0, acc[1][0]);
            wmma::mma_sync(acc[1][1], a1, b1, acc[1][1]);
        }
        __syncthreads();
    }

#pragma unroll
    for (int i = 0; i < 2; i++)
#pragma unroll
        for (int j = 0; j < 2; j++)
            wmma::store_matrix_sync(
                &C[(size_t)(m0 + wm * 32 + i * 16) * D + n0 + wn * 32 + j * 16],
                acc[i][j], D, wmma::mem_row_major);
}

// merged Q/K/V/U projection: virtual B = concat(Wq,Wk,Wv,Wu), N = 3072
__global__ void __launch_bounds__(256) gemm_qkvu_tc() {
    int nglob = blockIdx.x * GBN;
    int z = nglob / D;
    int n0 = nglob % D;
    float* Cs[4] = {g_q, g_k, g_v, g_u};
    gemm_body(g_Xh, g_Xl, g_Wh + (size_t)z * D * D, g_Wl + (size_t)z * D * D,
              Cs[z], blockIdx.y * GBM, n0);
}

__global__ void __launch_bounds__(256) gemm_out_tc(float* __restrict__ out) {
    gemm_body(g_lnh, g_lnl, g_Wh + (size_t)4 * D * D, g_Wl + (size_t)4 * D * D,
              out, blockIdx.y * GBM, blockIdx.x * GBN);
}

// ---------------- fp32 NT GEMM (kept for small gate matmul) -----------------
__device__ __forceinline__ void gemm_nt_body(const float* __restrict__ A,
                                             const float* __restrict__ B,
                                             float* __restrict__ C,
                                             int N, int K) {
    __shared__ float As[16 * 68];
    __shared__ float Bs[16 * 68];
    const int tid = threadIdx.x;
    const int tx = tid & 15, ty = tid >> 4;
    const int m0 = blockIdx.y * 64, n0 = blockIdx.x * 64;
    const int lr = tid >> 2;
    const int lk = (tid & 3) * 4;

    float acc[4][4];
#pragma unroll
    for (int i = 0; i < 4; i++)
#pragma unroll
        for (int j = 0; j < 4; j++) acc[i][j] = 0.f;

    const float* Ap = A + (size_t)(m0 + lr) * K + lk;
    const int brow = n0 + lr;
    const float* Bp = B + (size_t)brow * K + lk;
    const bool bv = brow < N;

    for (int kt = 0; kt < K; kt += 16) {
        float4 a = *(const float4*)(Ap + kt);
        float4 b = bv ? *(const float4*)(Bp + kt) : make_float4(0.f, 0.f, 0.f, 0.f);
        __syncthreads();
        As[(lk + 0) * 68 + lr] = a.x;
        As[(lk + 1) * 68 + lr] = a.y;
        As[(lk + 2) * 68 + lr] = a.z;
        As[(lk + 3) * 68 + lr] = a.w;
        Bs[(lk + 0) * 68 + lr] = b.x;
        Bs[(lk + 1) * 68 + lr] = b.y;
        Bs[(lk + 2) * 68 + lr] = b.z;
        Bs[(lk + 3) * 68 + lr] = b.w;
        __syncthreads();
#pragma unroll
        for (int kk = 0; kk < 16; kk++) {
            float4 av = *(const float4*)&As[kk * 68 + ty * 4];
            float4 bv4 = *(const float4*)&Bs[kk * 68 + tx * 4];
            float ar[4] = {av.x, av.y, av.z, av.w};
            float br[4] = {bv4.x, bv4.y, bv4.z, bv4.w};
#pragma unroll
            for (int i = 0; i < 4; i++)
#pragma unroll
                for (int j = 0; j < 4; j++) acc[i][j] = fmaf(ar[i], br[j], acc[i][j]);
        }
    }

#pragma unroll
    for (int i = 0; i < 4; i++) {
        int row = m0 + ty * 4 + i;
        int col0 = n0 + tx * 4;
        if (col0 + 3 < N) {
            float4 o = make_float4(acc[i][0], acc[i][1], acc[i][2], acc[i][3]);
            *(float4*)&C[(size_t)row * N + col0] = o;
        } else {
#pragma unroll
            for (int j = 0; j < 4; j++)
                if (col0 + j < N) C[(size_t)row * N + col0 + j] = acc[i][j];
        }
    }
}

__global__ void __launch_bounds__(256) gemm_gate(const float* __restrict__ X,
                                                 const float* __restrict__ Wg) {
    gemm_nt_body(X, Wg, g_gate, 36, D);
}

// ---------------- cumsum of u over L: coalesced smem-staged warp scan -------
__global__ void __launch_bounds__(256) cumsum_u_fast() {
    __shared__ float sm[32][9];
    const int c0 = blockIdx.x * 8;
    const int tid = threadIdx.x;
    const int w = tid >> 5, lane = tid & 31;
    const int lr = tid >> 3, lc = tid & 7;  // coalesced load mapping
    float carry = 0.f;
#pragma unroll 1
    for (int l0 = 0; l0 < L; l0 += 32) {
        float vin = g_u[(l0 + lr) * D + c0 + lc];
        __syncthreads();
        sm[lr][lc] = vin;
        __syncthreads();
        float v = sm[lane][w];  // warp w scans channel c0+w over 32 rows
#pragma unroll
        for (int o = 1; o < 32; o <<= 1) {
            float n = __shfl_up_sync(0xffffffffu, v, o);
            if (lane >= o) v += n;
        }
        v += carry;
        carry = __shfl_sync(0xffffffffu, v, 31);
        sm[lane][w] = v;
        __syncthreads();
        g_usum[(l0 + lr) * D + c0 + lc] = sm[lr][lc];
    }
}

// ---------------- s_i = -(1/sqrt(d)) * u . bar_u ----------------------------
__global__ void compute_s(const float* __restrict__ pmu,
                          const float* __restrict__ plt) {
    int gw = (blockIdx.x * blockDim.x + threadIdx.x) >> 5;
    int lane = threadIdx.x & 31;
    if (gw >= LH) return;
    int l = gw / NH, h = gw % NH;
    float lt = expf(fminf(fmaxf(plt[h], -50.f), 30.f));
    float t = (float)(l + 1);
    float inv_den = 1.f / (lt + t);
    float acc = 0.f;
#pragma unroll
    for (int r = 0; r < 2; r++) {
        int i = lane + r * 32;
        float uu = g_u[l * D + h * HD + i];
        float bu = (lt * pmu[h * HD + i] + g_usum[l * D + h * HD + i]) * inv_den;
        acc = fmaf(uu, bu, acc);
    }
#pragma unroll
    for (int o = 16; o; o >>= 1) acc += __shfl_xor_sync(0xffffffffu, acc, o);
    if (lane == 0) g_s[l * NH + h] = -acc * 0.125f;
}

// ---------------- per-head: max, scans, gate coefficients -------------------
__global__ void __launch_bounds__(1024) head_scan() {
    __shared__ float she[1024];
    __shared__ float shp[1024];
    const int h = blockIdx.x;
    const int l = threadIdx.x;
    float s = g_s[l * NH + h];
    she[l] = s;
    __syncthreads();
    for (int off = 512; off > 0; off >>= 1) {
        if (l < off) she[l] = fmaxf(she[l], she[l + off]);
        __syncthreads();
    }
    float smax = she[0];
    __syncthreads();
    float e = expf(s - smax);
    float ev = e, pv = s;
    she[l] = ev;
    shp[l] = pv;
    __syncthreads();
    for (int off = 1; off < 1024; off <<= 1) {
        float ae = 0.f, ap = 0.f;
        if (l >= off) { ae = she[l - off]; ap = shp[l - off]; }
        __syncthreads();
        ev += ae;
        pv += ap;
        she[l] = ev;
        shp[l] = pv;
        __syncthreads();
    }
    float g1 = g_gate[l * 36 + h * 3 + 0];
    float gh = g_gate[l * 36 + h * 3 + 1];
    float s1 = 1.f / (1.f + expf(-g1));
    float shg = 1.f / (1.f + expf(-gh));
    float t = (float)(l + 1);
    float a = shg / (ev + 1e-12f);
    float b = (s1 - shg) / t;
    float gm = -(b * pv + shg) / t;
    int o = l * NH + h;
    g_es[o] = e;
    g_al[o] = a;
    g_be[o] = b;
    g_ga[o] = gm;
}

// ---------------- RoPE + L2 normalize on q, k (fp32) ------------------------
__global__ void rope_norm() {
    int gw = (blockIdx.x * blockDim.x + threadIdx.x) >> 5;
    int lane = threadIdx.x & 31;
    if (gw >= LH) return;
    int l = gw / NH, h = gw % NH;
    int base = l * D + h * HD;
    int i0 = lane >> 1;
    const float LN1E4_32 = 0.28782313662425572f;  // ln(10000)/32
    float f0 = expf(-(float)i0 * LN1E4_32);
    float f1 = expf(-(float)(i0 + 16) * LN1E4_32);
    float a0 = (float)l * f0;
    float a1 = (float)l * f1;
    float c0 = cosf(a0), sn0 = sinf(a0);
    float c1 = cosf(a1), sn1 = sinf(a1);

    {
        float x0 = g_q[base + lane], x1 = g_q[base + lane + 32];
        float r0 = x0 * c0 - x1 * sn0;
        float r1 = x1 * c1 + x0 * sn1;
        float nn = r0 * r0 + r1 * r1;
#pragma unroll
        for (int o = 16; o; o >>= 1) nn += __shfl_xor_sync(0xffffffffu, nn, o);
        float inv = 1.f / fmaxf(sqrtf(nn), 1e-12f);
        g_q[base + lane] = r0 * inv;
        g_q[base + lane + 32] = r1 * inv;
    }
    {
        float x0 = g_k[base + lane], x1 = g_k[base + lane + 32];
        float r0 = x0 * c0 - x1 * sn0;
        float r1 = x1 * c1 + x0 * sn1;
        float nn = r0 * r0 + r1 * r1;
#pragma unroll
        for (int o = 16; o; o >>= 1) nn += __shfl_xor_sync(0xffffffffu, nn, o);
        float inv = 1.f / fmaxf(sqrtf(nn), 1e-12f);
        g_k[base + lane] = r0 * inv;
        g_k[base + lane + 32] = r1 * inv;
    }
}

// ---------------- weighted causal attention + fused LayerNorm ---------------
// out_l = sum_{j<=l} (q_l.k_j) * (al_l*es_j + be_l*s_j + ga_l) * v_j
#define ATTN_SMEM ((2 * 64 * 68 + 64 * 64) * 4)

__global__ void __launch_bounds__(256) attn_kernel() {
    extern __shared__ float smem[];
    float* Qs = smem;                 // [d][m], stride 68
    float* KSs = smem + 64 * 68;      // [d][j] then reused as S^T [j][m]
    float* Vs = smem + 2 * 64 * 68;   // [j][e], stride 64
    __shared__ float cA[64], cB[64], cG[64], sES[64], sS[64];

    const int h = blockIdx.y;
    const int lt = 15 - blockIdx.x;
    const int l0 = lt * 64;
    const int tid = threadIdx.x;
    const int tx = tid & 15, ty = tid >> 4;

#pragma unroll
    for (int it = 0; it < 4; it++) {
        int idx = tid + it * 256;
        int row = idx >> 4;
        int c4 = (idx & 15) << 2;
        float4 x = *(const float4*)(g_q + (l0 + row) * D + h * HD + c4);
        Qs[(c4 + 0) * 68 + row] = x.x;
        Qs[(c4 + 1) * 68 + row] = x.y;
        Qs[(c4 + 2) * 68 + row] = x.z;
        Qs[(c4 + 3) * 68 + row] = x.w;
    }
    if (tid < 64) {
        cA[tid] = g_al[(l0 + tid) * NH + h];
        cB[tid] = g_be[(l0 + tid) * NH + h];
        cG[tid] = g_ga[(l0 + tid) * NH + h];
    }

    float oacc[4][4];
#pragma unroll
    for (int i = 0; i < 4; i++)
#pragma unroll
        for (int j = 0; j < 4; j++) oacc[i][j] = 0.f;

    for (int jt = 0; jt <= lt; jt++) {
        const int j0 = jt * 64;
        __syncthreads();
#pragma unroll
        for (int it = 0; it < 4; it++) {
            int idx = tid + it * 256;
            int row = idx >> 4;
            int c4 = (idx & 15) << 2;
            float4 xk = *(const float4*)(g_k + (j0 + row) * D + h * HD + c4);
            KSs[(c4 + 0) * 68 + row] = xk.x;
            KSs[(c4 + 1) * 68 + row] = xk.y;
            KSs[(c4 + 2) * 68 + row] = xk.z;
            KSs[(c4 + 3) * 68 + row] = xk.w;
            float4 xv = *(const float4*)(g_v + (j0 + row) * D + h * HD + c4);
            *(float4*)&Vs[row * 64 + c4] = xv;
        }
        if (tid < 64) {
            sES[tid] = g_es[(j0 + tid) * NH + h];
            sS[tid] = g_s[(j0 + tid) * NH + h];
        }
        __syncthreads();

        float sacc[4][4];
#pragma unroll
        for (int i = 0; i < 4; i++)
#pragma unroll
            for (int j = 0; j < 4; j++) sacc[i][j] = 0.f;
#pragma unroll 8
        for (int kk = 0; kk < 64; kk++) {
            float4 av = *(const float4*)&Qs[kk * 68 + ty * 4];
            float4 bv = *(const float4*)&KSs[kk * 68 + tx * 4];
            float ar[4] = {av.x, av.y, av.z, av.w};
            float br[4] = {bv.x, bv.y, bv.z, bv.w};
#pragma unroll
            for (int i = 0; i < 4; i++)
#pragma unroll
                for (int j = 0; j < 4; j++) sacc[i][j] = fmaf(ar[i], br[j], sacc[i][j]);
        }
        __syncthreads();

#pragma unroll
        for (int i = 0; i < 4; i++) {
            int r = ty * 4 + i;
            int gl = l0 + r;
            float Ar = cA[r], Br = cB[r], Gr = cG[r];
#pragma unroll
            for (int j = 0; j < 4; j++) {
                int c = tx * 4 + j;
                int gj = j0 + c;
                float w = Ar * sES[c] + Br * sS[c] + Gr;
                KSs[c * 68 + r] = (gj <= gl) ? sacc[i][j] * w : 0.f;
            }
        }
        __syncthreads();

#pragma unroll 8
        for (int c = 0; c < 64; c++) {
            float4 av = *(const float4*)&KSs[c * 68 + ty * 4];
            float4 bv = *(const float4*)&Vs[c * 64 + tx * 4];
            float ar[4] = {av.x, av.y, av.z, av.w};
            float br[4] = {bv.x, bv.y, bv.z, bv.w};
#pragma unroll
            for (int i = 0; i < 4; i++)
#pragma unroll
                for (int j = 0; j < 4; j++) oacc[i][j] = fmaf(ar[i], br[j], oacc[i][j]);
        }
    }

    // fused LayerNorm, emit split-bf16 for the Wo GEMM
#pragma unroll
    for (int i = 0; i < 4; i++) {
        float sum = oacc[i][0] + oacc[i][1] + oacc[i][2] + oacc[i][3];
#pragma unroll
        for (int o = 8; o; o >>= 1) sum += __shfl_xor_sync(0xffffffffu, sum, o);
        float mean = sum * (1.f / 64.f);
        float d0 = oacc[i][0] - mean, d1 = oacc[i][1] - mean;
        float d2 = oacc[i][2] - mean, d3 = oacc[i][3] - mean;
        float vs = d0 * d0 + d1 * d1 + d2 * d2 + d3 * d3;
#pragma unroll
        for (int o = 8; o; o >>= 1) vs += __shfl_xor_sync(0xffffffffu, vs, o);
        float inv = rsqrtf(vs * (1.f / 64.f) + 1e-5f);
        float v0 = d0 * inv, v1 = d1 * inv, v2 = d2 * inv, v3 = d3 * inv;

        int off = (l0 + ty * 4 + i) * D + h * HD + tx * 4;
        __nv_bfloat16 h0 = __float2bfloat16(v0);
        __nv_bfloat16 h1 = __float2bfloat16(v1);
        __nv_bfloat16 h2 = __float2bfloat16(v2);
        __nv_bfloat16 h3 = __float2bfloat16(v3);
        __nv_bfloat162 hp0 = __nv_bfloat162(h0, h1);
        __nv_bfloat162 hp1 = __nv_bfloat162(h2, h3);
        *(__nv_bfloat162*)&g_lnh[off] = hp0;
        *(__nv_bfloat162*)&g_lnh[off + 2] = hp1;
        __nv_bfloat162 lp0 = __nv_bfloat162(
            __float2bfloat16(v0 - __bfloat162float(h0)),
            __float2bfloat16(v1 - __bfloat162float(h1)));
        __nv_bfloat162 lp1 = __nv_bfloat162(
            __float2bfloat16(v2 - __bfloat162float(h2)),
            __float2bfloat16(v3 - __bfloat162float(h3)));
        *(__nv_bfloat162*)&g_lnl[off] = lp0;
        *(__nv_bfloat162*)&g_lnl[off + 2] = lp1;
    }
}

// ---------------- launch ----------------------------------------------------
extern "C" void kernel_launch(void* const* d_in, const int* in_sizes, int n_in,
                              void* d_out, int out_size) {
    const float* X = (const float*)d_in[0];
    const float* Wq = (const float*)d_in[1];
    const float* Wk = (const float*)d_in[2];
    const float* Wv = (const float*)d_in[3];
    const float* Wu = (const float*)d_in[4];
    const float* Wg = (const float*)d_in[5];
    const float* Wo = (const float*)d_in[6];
    const float* pmu = (const float*)d_in[7];
    const float* plt = (const float*)d_in[8];
    float* out = (float*)d_out;

    cudaFuncSetAttribute(attn_kernel, cudaFuncAttributeMaxDynamicSharedMemorySize,
                         ATTN_SMEM);
    cudaFuncSetAttribute(gemm_qkvu_tc, cudaFuncAttributeMaxDynamicSharedMemorySize,
                         GEMM_SMEM);
    cudaFuncSetAttribute(gemm_out_tc, cudaFuncAttributeMaxDynamicSharedMemorySize,
                         GEMM_SMEM);

    // split-bf16 conversion of X and weights
    convert_inputs<<<dim3(96, 6), 256>>>(X, Wq, Wk, Wv, Wu, Wo);

    // merged Q/K/V/U projection on tensor cores (double-buffered cp.async)
    gemm_qkvu_tc<<<dim3(4 * D / GBN, L / GBM), 256, GEMM_SMEM>>>();
    gemm_gate<<<dim3(1, L / 64), 256>>>(X, Wg);

    // logits pipeline (coalesced warp-scan cumsum)
    cumsum_u_fast<<<D / 8, 256>>>();
    compute_s<<<(LH * 32 + 255) / 256, 256>>>(pmu, plt);
    head_scan<<<NH, 1024>>>();

    // RoPE + normalize
    rope_norm<<<(LH * 32 + 255) / 256, 256>>>();

    // attention + fused LayerNorm (emits split-bf16)
    attn_kernel<<<dim3(16, NH), 256, ATTN_SMEM>>>();

    // output projection on tensor cores
    gemm_out_tc<<<dim3(D / GBN, L / GBM), 256, GEMM_SMEM>>>(out);
}

// round 6
// speedup vs baseline: 2.6985x; 1.2175x over previous
#include <cuda_runtime.h>
#include <cuda_bf16.h>
#include <mma.h>
#include <math.h>
#include <cstdint>

using namespace nvcuda;

#define L 1024
#define D 768
#define NH 12
#define HD 64
#define LH (L*NH)

// ---------------- scratch (device globals; no allocation allowed) ----------
__device__ float g_q[L*D];
__device__ float g_k[L*D];
__device__ float g_v[L*D];
__device__ float g_u[L*D];
__device__ float g_usum[L*D];
__device__ float g_gate[L*36];
__device__ float g_s[LH];
__device__ float g_es[LH];
__device__ float g_al[LH];
__device__ float g_be[LH];
__device__ float g_ga[LH];

// split-bf16 buffers
__device__ __nv_bfloat16 g_Xh[L*D];
__device__ __nv_bfloat16 g_Xl[L*D];
__device__ __nv_bfloat16 g_Wh[5*D*D];   // Wq,Wk,Wv,Wu,Wo
__device__ __nv_bfloat16 g_Wl[5*D*D];
__device__ __nv_bfloat16 g_lnh[L*D];
__device__ __nv_bfloat16 g_lnl[L*D];
// split q/k/v for tensor-core attention
__device__ __nv_bfloat16 g_qh[L*D];
__device__ __nv_bfloat16 g_ql[L*D];
__device__ __nv_bfloat16 g_kh[L*D];
__device__ __nv_bfloat16 g_kl[L*D];
__device__ __nv_bfloat16 g_vh[L*D];
__device__ __nv_bfloat16 g_vl[L*D];

// ---------------- fp32 -> (hi, lo) bf16 conversion --------------------------
__global__ void convert_inputs(const float* __restrict__ X,
                               const float* __restrict__ Wq,
                               const float* __restrict__ Wk,
                               const float* __restrict__ Wv,
                               const float* __restrict__ Wu,
                               const float* __restrict__ Wo) {
    int z = blockIdx.y;
    const float* src;
    __nv_bfloat16 *dh, *dl;
    int n;
    if (z == 0) { src = X; dh = g_Xh; dl = g_Xl; n = L * D; }
    else {
        const float* ws[5] = {Wq, Wk, Wv, Wu, Wo};
        src = ws[z - 1];
        dh = g_Wh + (z - 1) * D * D;
        dl = g_Wl + (z - 1) * D * D;
        n = D * D;
    }
    for (int i = blockIdx.x * blockDim.x + threadIdx.x; i < n;
         i += gridDim.x * blockDim.x) {
        float v = src[i];
        __nv_bfloat16 h = __float2bfloat16(v);
        dh[i] = h;
        dl[i] = __float2bfloat16(v - __bfloat162float(h));
    }
}

// ---------------- cp.async helpers ------------------------------------------
__device__ __forceinline__ void cp16(void* dst, const void* src) {
    unsigned d = (unsigned)__cvta_generic_to_shared(dst);
    asm volatile("cp.async.cg.shared.global [%0], [%1], 16;" :: "r"(d), "l"(src));
}

// ---------------- split-bf16 tensor-core GEMM (double-buffered cp.async) ----
#define GBM 128
#define GBN 64
#define GBK 64
#define GLD 72
#define GEMM_SMEM ((GBM + GBN) * GLD * 2 * 2)   // 55296 bytes

__device__ __forceinline__ void gemm_stage_load(
    __nv_bfloat16* As, __nv_bfloat16* Bs,
    const __nv_bfloat16* __restrict__ A, const __nv_bfloat16* __restrict__ B,
    int m0, int n0, int kt, int tid) {
#pragma unroll
    for (int i = 0; i < 4; i++) {
        int idx = tid + i * 256;
        int r = idx >> 3, c8 = (idx & 7) * 8;
        cp16(&As[r * GLD + c8], &A[(size_t)(m0 + r) * D + kt + c8]);
    }
#pragma unroll
    for (int i = 0; i < 2; i++) {
        int idx = tid + i * 256;
        int r = idx >> 3, c8 = (idx & 7) * 8;
        cp16(&Bs[r * GLD + c8], &B[(size_t)(n0 + r) * D + kt + c8]);
    }
    asm volatile("cp.async.commit_group;");
}

__device__ __forceinline__ void gemm_body(
    const __nv_bfloat16* __restrict__ Ah, const __nv_bfloat16* __restrict__ Al,
    const __nv_bfloat16* __restrict__ Bh, const __nv_bfloat16* __restrict__ Bl,
    float* __restrict__ C, int m0, int n0) {
    extern __shared__ __nv_bfloat16 sh[];
    __nv_bfloat16* Asb[2] = {sh, sh + (GBM + GBN) * GLD};
    __nv_bfloat16* Bsb[2] = {sh + GBM * GLD, sh + (GBM + GBN) * GLD + GBM * GLD};

    const int tid = threadIdx.x;
    const int warp = tid >> 5;
    const int wm = warp >> 1, wn = warp & 1;

    wmma::fragment<wmma::accumulator, 16, 16, 16, float> acc[2][2];
#pragma unroll
    for (int i = 0; i < 2; i++)
#pragma unroll
        for (int j = 0; j < 2; j++) wmma::fill_fragment(acc[i][j], 0.f);

    const int NIT = 36;
    auto getAB = [&](int it, const __nv_bfloat16*& A, const __nv_bfloat16*& B,
                     int& kt) {
        int seg = it / 12;
        kt = (it % 12) * GBK;
        A = (seg == 1) ? Al : Ah;
        B = (seg == 2) ? Bl : Bh;
    };

    {
        const __nv_bfloat16 *A, *B;
        int kt;
        getAB(0, A, B, kt);
        gemm_stage_load(Asb[0], Bsb[0], A, B, m0, n0, kt, tid);
    }

#pragma unroll 1
    for (int it = 0; it < NIT; it++) {
        if (it + 1 < NIT) {
            const __nv_bfloat16 *A, *B;
            int kt;
            getAB(it + 1, A, B, kt);
            gemm_stage_load(Asb[(it + 1) & 1], Bsb[(it + 1) & 1], A, B, m0, n0,
                            kt, tid);
            asm volatile("cp.async.wait_group 1;");
        } else {
            asm volatile("cp.async.wait_group 0;");
        }
        __syncthreads();

        const __nv_bfloat16* As = Asb[it & 1];
        const __nv_bfloat16* Bs = Bsb[it & 1];
#pragma unroll
        for (int kk = 0; kk < GBK; kk += 16) {
            wmma::fragment<wmma::matrix_a, 16, 16, 16, __nv_bfloat16,
                           wmma::row_major> a0, a1;
            wmma::fragment<wmma::matrix_b, 16, 16, 16, __nv_bfloat16,
                           wmma::col_major> b0, b1;
            wmma::load_matrix_sync(a0, &As[(wm * 32) * GLD + kk], GLD);
            wmma::load_matrix_sync(a1, &As[(wm * 32 + 16) * GLD + kk], GLD);
            wmma::load_matrix_sync(b0, &Bs[(wn * 32) * GLD + kk], GLD);
            wmma::load_matrix_sync(b1, &Bs[(wn * 32 + 16) * GLD + kk], GLD);
            wmma::mma_sync(acc[0][0], a0, b0, acc[0][0]);
            wmma::mma_sync(acc[0][1], a0, b1, acc[0][1]);
            wmma::mma_sync(acc[1][0], a1, b0, acc[1][0]);
            wmma::mma_sync(acc[1][1], a1, b1, acc[1][1]);
        }
        __syncthreads();
    }

#pragma unroll
    for (int i = 0; i < 2; i++)
#pragma unroll
        for (int j = 0; j < 2; j++)
            wmma::store_matrix_sync(
                &C[(size_t)(m0 + wm * 32 + i * 16) * D + n0 + wn * 32 + j * 16],
                acc[i][j], D, wmma::mem_row_major);
}

__global__ void __launch_bounds__(256) gemm_qkvu_tc() {
    int nglob = blockIdx.x * GBN;
    int z = nglob / D;
    int n0 = nglob % D;
    float* Cs[4] = {g_q, g_k, g_v, g_u};
    gemm_body(g_Xh, g_Xl, g_Wh + (size_t)z * D * D, g_Wl + (size_t)z * D * D,
              Cs[z], blockIdx.y * GBM, n0);
}

__global__ void __launch_bounds__(256) gemm_out_tc(float* __restrict__ out) {
    gemm_body(g_lnh, g_lnl, g_Wh + (size_t)4 * D * D, g_Wl + (size_t)4 * D * D,
              out, blockIdx.y * GBM, blockIdx.x * GBN);
}

// ---------------- fp32 NT GEMM (small gate matmul) --------------------------
__device__ __forceinline__ void gemm_nt_body(const float* __restrict__ A,
                                             const float* __restrict__ B,
                                             float* __restrict__ C,
                                             int N, int K) {
    __shared__ float As[16 * 68];
    __shared__ float Bs[16 * 68];
    const int tid = threadIdx.x;
    const int tx = tid & 15, ty = tid >> 4;
    const int m0 = blockIdx.y * 64, n0 = blockIdx.x * 64;
    const int lr = tid >> 2;
    const int lk = (tid & 3) * 4;

    float acc[4][4];
#pragma unroll
    for (int i = 0; i < 4; i++)
#pragma unroll
        for (int j = 0; j < 4; j++) acc[i][j] = 0.f;

    const float* Ap = A + (size_t)(m0 + lr) * K + lk;
    const int brow = n0 + lr;
    const float* Bp = B + (size_t)brow * K + lk;
    const bool bv = brow < N;

    for (int kt = 0; kt < K; kt += 16) {
        float4 a = *(const float4*)(Ap + kt);
        float4 b = bv ? *(const float4*)(Bp + kt) : make_float4(0.f, 0.f, 0.f, 0.f);
        __syncthreads();
        As[(lk + 0) * 68 + lr] = a.x;
        As[(lk + 1) * 68 + lr] = a.y;
        As[(lk + 2) * 68 + lr] = a.z;
        As[(lk + 3) * 68 + lr] = a.w;
        Bs[(lk + 0) * 68 + lr] = b.x;
        Bs[(lk + 1) * 68 + lr] = b.y;
        Bs[(lk + 2) * 68 + lr] = b.z;
        Bs[(lk + 3) * 68 + lr] = b.w;
        __syncthreads();
#pragma unroll
        for (int kk = 0; kk < 16; kk++) {
            float4 av = *(const float4*)&As[kk * 68 + ty * 4];
            float4 bv4 = *(const float4*)&Bs[kk * 68 + tx * 4];
            float ar[4] = {av.x, av.y, av.z, av.w};
            float br[4] = {bv4.x, bv4.y, bv4.z, bv4.w};
#pragma unroll
            for (int i = 0; i < 4; i++)
#pragma unroll
                for (int j = 0; j < 4; j++) acc[i][j] = fmaf(ar[i], br[j], acc[i][j]);
        }
    }

#pragma unroll
    for (int i = 0; i < 4; i++) {
        int row = m0 + ty * 4 + i;
        int col0 = n0 + tx * 4;
        if (col0 + 3 < N) {
            float4 o = make_float4(acc[i][0], acc[i][1], acc[i][2], acc[i][3]);
            *(float4*)&C[(size_t)row * N + col0] = o;
        } else {
#pragma unroll
            for (int j = 0; j < 4; j++)
                if (col0 + j < N) C[(size_t)row * N + col0 + j] = acc[i][j];
        }
    }
}

__global__ void __launch_bounds__(256) gemm_gate(const float* __restrict__ X,
                                                 const float* __restrict__ Wg) {
    gemm_nt_body(X, Wg, g_gate, 36, D);
}

// ---------------- cumsum of u over L: coalesced smem-staged warp scan -------
__global__ void __launch_bounds__(256) cumsum_u_fast() {
    __shared__ float sm[32][9];
    const int c0 = blockIdx.x * 8;
    const int tid = threadIdx.x;
    const int w = tid >> 5, lane = tid & 31;
    const int lr = tid >> 3, lc = tid & 7;
    float carry = 0.f;
#pragma unroll 1
    for (int l0 = 0; l0 < L; l0 += 32) {
        float vin = g_u[(l0 + lr) * D + c0 + lc];
        __syncthreads();
        sm[lr][lc] = vin;
        __syncthreads();
        float v = sm[lane][w];
#pragma unroll
        for (int o = 1; o < 32; o <<= 1) {
            float n = __shfl_up_sync(0xffffffffu, v, o);
            if (lane >= o) v += n;
        }
        v += carry;
        carry = __shfl_sync(0xffffffffu, v, 31);
        sm[lane][w] = v;
        __syncthreads();
        g_usum[(l0 + lr) * D + c0 + lc] = sm[lr][lc];
    }
}

// ---------------- s_i = -(1/sqrt(d)) * u . bar_u ----------------------------
__global__ void compute_s(const float* __restrict__ pmu,
                          const float* __restrict__ plt) {
    int gw = (blockIdx.x * blockDim.x + threadIdx.x) >> 5;
    int lane = threadIdx.x & 31;
    if (gw >= LH) return;
    int l = gw / NH, h = gw % NH;
    float lt = expf(fminf(fmaxf(plt[h], -50.f), 30.f));
    float t = (float)(l + 1);
    float inv_den = 1.f / (lt + t);
    float acc = 0.f;
#pragma unroll
    for (int r = 0; r < 2; r++) {
        int i = lane + r * 32;
        float uu = g_u[l * D + h * HD + i];
        float bu = (lt * pmu[h * HD + i] + g_usum[l * D + h * HD + i]) * inv_den;
        acc = fmaf(uu, bu, acc);
    }
#pragma unroll
    for (int o = 16; o; o >>= 1) acc += __shfl_xor_sync(0xffffffffu, acc, o);
    if (lane == 0) g_s[l * NH + h] = -acc * 0.125f;
}

// ---------------- per-head: max, scans, gate coefficients -------------------
__global__ void __launch_bounds__(1024) head_scan() {
    __shared__ float she[1024];
    __shared__ float shp[1024];
    const int h = blockIdx.x;
    const int l = threadIdx.x;
    float s = g_s[l * NH + h];
    she[l] = s;
    __syncthreads();
    for (int off = 512; off > 0; off >>= 1) {
        if (l < off) she[l] = fmaxf(she[l], she[l + off]);
        __syncthreads();
    }
    float smax = she[0];
    __syncthreads();
    float e = expf(s - smax);
    float ev = e, pv = s;
    she[l] = ev;
    shp[l] = pv;
    __syncthreads();
    for (int off = 1; off < 1024; off <<= 1) {
        float ae = 0.f, ap = 0.f;
        if (l >= off) { ae = she[l - off]; ap = shp[l - off]; }
        __syncthreads();
        ev += ae;
        pv += ap;
        she[l] = ev;
        shp[l] = pv;
        __syncthreads();
    }
    float g1 = g_gate[l * 36 + h * 3 + 0];
    float gh = g_gate[l * 36 + h * 3 + 1];
    float s1 = 1.f / (1.f + expf(-g1));
    float shg = 1.f / (1.f + expf(-gh));
    float t = (float)(l + 1);
    float a = shg / (ev + 1e-12f);
    float b = (s1 - shg) / t;
    float gm = -(b * pv + shg) / t;
    int o = l * NH + h;
    g_es[o] = e;
    g_al[o] = a;
    g_be[o] = b;
    g_ga[o] = gm;
}

// ---------------- RoPE + L2 normalize; emit split-bf16 q/k/v ----------------
__device__ __forceinline__ void split_store(__nv_bfloat16* dh, __nv_bfloat16* dl,
                                            int idx, float v) {
    __nv_bfloat16 hb = __float2bfloat16(v);
    dh[idx] = hb;
    dl[idx] = __float2bfloat16(v - __bfloat162float(hb));
}

__global__ void rope_norm() {
    int gw = (blockIdx.x * blockDim.x + threadIdx.x) >> 5;
    int lane = threadIdx.x & 31;
    if (gw >= LH) return;
    int l = gw / NH, h = gw % NH;
    int base = l * D + h * HD;
    int i0 = lane >> 1;
    const float LN1E4_32 = 0.28782313662425572f;
    float f0 = expf(-(float)i0 * LN1E4_32);
    float f1 = expf(-(float)(i0 + 16) * LN1E4_32);
    float a0 = (float)l * f0;
    float a1 = (float)l * f1;
    float c0 = cosf(a0), sn0 = sinf(a0);
    float c1 = cosf(a1), sn1 = sinf(a1);

    {
        float x0 = g_q[base + lane], x1 = g_q[base + lane + 32];
        float r0 = x0 * c0 - x1 * sn0;
        float r1 = x1 * c1 + x0 * sn1;
        float nn = r0 * r0 + r1 * r1;
#pragma unroll
        for (int o = 16; o; o >>= 1) nn += __shfl_xor_sync(0xffffffffu, nn, o);
        float inv = 1.f / fmaxf(sqrtf(nn), 1e-12f);
        split_store(g_qh, g_ql, base + lane, r0 * inv);
        split_store(g_qh, g_ql, base + lane + 32, r1 * inv);
    }
    {
        float x0 = g_k[base + lane], x1 = g_k[base + lane + 32];
        float r0 = x0 * c0 - x1 * sn0;
        float r1 = x1 * c1 + x0 * sn1;
        float nn = r0 * r0 + r1 * r1;
#pragma unroll
        for (int o = 16; o; o >>= 1) nn += __shfl_xor_sync(0xffffffffu, nn, o);
        float inv = 1.f / fmaxf(sqrtf(nn), 1e-12f);
        split_store(g_kh, g_kl, base + lane, r0 * inv);
        split_store(g_kh, g_kl, base + lane + 32, r1 * inv);
    }
    {
        split_store(g_vh, g_vl, base + lane, g_v[base + lane]);
        split_store(g_vh, g_vl, base + lane + 32, g_v[base + lane + 32]);
    }
}

// ---------------- tensor-core weighted causal attention + LayerNorm ---------
// out_l = sum_{j<=l} (q_l.k_j) * (al_l*es_j + be_l*s_j + ga_l) * v_j
#define ALD 72   // bf16 tile ld
#define SLD 68   // fp32 S/O ld
// smem: Qh Ql Kh Kl Vh Vl Sh Sl (8 x 64*72 bf16) + Sf (64*68 fp32)
#define ATTN_SMEM (8 * 64 * ALD * 2 + 64 * SLD * 4)

__global__ void __launch_bounds__(256) attn_tc() {
    extern __shared__ __nv_bfloat16 ash[];
    __nv_bfloat16* Qh = ash;
    __nv_bfloat16* Ql = ash + 1 * 64 * ALD;
    __nv_bfloat16* Kh = ash + 2 * 64 * ALD;
    __nv_bfloat16* Kl = ash + 3 * 64 * ALD;
    __nv_bfloat16* Vh = ash + 4 * 64 * ALD;
    __nv_bfloat16* Vl = ash + 5 * 64 * ALD;
    __nv_bfloat16* Sh = ash + 6 * 64 * ALD;
    __nv_bfloat16* Sl = ash + 7 * 64 * ALD;
    float* Sf = (float*)(ash + 8 * 64 * ALD);
    __shared__ float cA[64], cB[64], cG[64], sES[64], sS[64];

    const int h = blockIdx.y;
    const int lt = 15 - blockIdx.x;  // heavy tiles first
    const int l0 = lt * 64;
    const int tid = threadIdx.x;
    const int warp = tid >> 5;
    const int wm = warp >> 1, wn = warp & 1;

    // load Q tiles (hi/lo)
#pragma unroll
    for (int it = 0; it < 2; it++) {
        int idx = tid + it * 256;
        int r = idx >> 3, c = (idx & 7) * 8;
        *(uint4*)&Qh[r * ALD + c] = *(const uint4*)&g_qh[(l0 + r) * D + h * HD + c];
        *(uint4*)&Ql[r * ALD + c] = *(const uint4*)&g_ql[(l0 + r) * D + h * HD + c];
    }
    if (tid < 64) {
        cA[tid] = g_al[(l0 + tid) * NH + h];
        cB[tid] = g_be[(l0 + tid) * NH + h];
        cG[tid] = g_ga[(l0 + tid) * NH + h];
    }

    wmma::fragment<wmma::accumulator, 16, 16, 16, float> acc_o[2];
    wmma::fill_fragment(acc_o[0], 0.f);
    wmma::fill_fragment(acc_o[1], 0.f);

    const int r_ = tid >> 2;            // row for weight step
    const int cb_ = (tid & 3) * 16;     // col base for weight step

#pragma unroll 1
    for (int jt = 0; jt <= lt; jt++) {
        const int j0 = jt * 64;
        __syncthreads();  // prev iter reads of K/V/Sh/Sl done; Q load visible
#pragma unroll
        for (int it = 0; it < 2; it++) {
            int idx = tid + it * 256;
            int r = idx >> 3, c = (idx & 7) * 8;
            *(uint4*)&Kh[r * ALD + c] = *(const uint4*)&g_kh[(j0 + r) * D + h * HD + c];
            *(uint4*)&Kl[r * ALD + c] = *(const uint4*)&g_kl[(j0 + r) * D + h * HD + c];
            *(uint4*)&Vh[r * ALD + c] = *(const uint4*)&g_vh[(j0 + r) * D + h * HD + c];
            *(uint4*)&Vl[r * ALD + c] = *(const uint4*)&g_vl[(j0 + r) * D + h * HD + c];
        }
        if (tid < 64) {
            sES[tid] = g_es[(j0 + tid) * NH + h];
            sS[tid] = g_s[(j0 + tid) * NH + h];
        }
        __syncthreads();

        // S = Q K^T : 3 passes (QhKh, QlKh, QhKl), K-major B (col_major)
        wmma::fragment<wmma::accumulator, 16, 16, 16, float> acc_s[2];
        wmma::fill_fragment(acc_s[0], 0.f);
        wmma::fill_fragment(acc_s[1], 0.f);
#pragma unroll
        for (int p = 0; p < 3; p++) {
            const __nv_bfloat16* Aq = (p == 1) ? Ql : Qh;
            const __nv_bfloat16* Bk = (p == 2) ? Kl : Kh;
#pragma unroll
            for (int kk = 0; kk < 64; kk += 16) {
                wmma::fragment<wmma::matrix_a, 16, 16, 16, __nv_bfloat16,
                               wmma::row_major> af;
                wmma::load_matrix_sync(af, &Aq[(wm * 16) * ALD + kk], ALD);
#pragma unroll
                for (int jn = 0; jn < 2; jn++) {
                    wmma::fragment<wmma::matrix_b, 16, 16, 16, __nv_bfloat16,
                                   wmma::col_major> bf;
                    wmma::load_matrix_sync(
                        bf, &Bk[(wn * 32 + jn * 16) * ALD + kk], ALD);
                    wmma::mma_sync(acc_s[jn], af, bf, acc_s[jn]);
                }
            }
        }
#pragma unroll
        for (int jn = 0; jn < 2; jn++)
            wmma::store_matrix_sync(&Sf[(wm * 16) * SLD + wn * 32 + jn * 16],
                                    acc_s[jn], SLD, wmma::mem_row_major);
        __syncthreads();

        // weight + causal mask + split-bf16 re-emit
        {
            float Ar = cA[r_], Br = cB[r_], Gr = cG[r_];
            int gl = l0 + r_;
#pragma unroll
            for (int i = 0; i < 16; i++) {
                int c = cb_ + i;
                float w = Ar * sES[c] + Br * sS[c] + Gr;
                float sv = (j0 + c <= gl) ? Sf[r_ * SLD + c] * w : 0.f;
                __nv_bfloat16 hb = __float2bfloat16(sv);
                Sh[r_ * ALD + c] = hb;
                Sl[r_ * ALD + c] = __float2bfloat16(sv - __bfloat162float(hb));
            }
        }
        __syncthreads();

        // O += S V : 3 passes (ShVh, SlVh, ShVl), V row-major B
#pragma unroll
        for (int p = 0; p < 3; p++) {
            const __nv_bfloat16* Asm = (p == 1) ? Sl : Sh;
            const __nv_bfloat16* Bvm = (p == 2) ? Vl : Vh;
#pragma unroll
            for (int kk = 0; kk < 64; kk += 16) {
                wmma::fragment<wmma::matrix_a, 16, 16, 16, __nv_bfloat16,
                               wmma::row_major> af;
                wmma::load_matrix_sync(af, &Asm[(wm * 16) * ALD + kk], ALD);
#pragma unroll
                for (int jn = 0; jn < 2; jn++) {
                    wmma::fragment<wmma::matrix_b, 16, 16, 16, __nv_bfloat16,
                                   wmma::row_major> bf;
                    wmma::load_matrix_sync(bf, &Bvm[kk * ALD + wn * 32 + jn * 16],
                                           ALD);
                    wmma::mma_sync(acc_o[jn], af, bf, acc_o[jn]);
                }
            }
        }
    }

    // O -> smem, fused LayerNorm over head dim, emit split-bf16
    __syncthreads();
#pragma unroll
    for (int jn = 0; jn < 2; jn++)
        wmma::store_matrix_sync(&Sf[(wm * 16) * SLD + wn * 32 + jn * 16],
                                acc_o[jn], SLD, wmma::mem_row_major);
    __syncthreads();
    {
        float vals[16];
        float sum = 0.f;
#pragma unroll
        for (int i = 0; i < 16; i++) {
            vals[i] = Sf[r_ * SLD + cb_ + i];
            sum += vals[i];
        }
        sum += __shfl_xor_sync(0xffffffffu, sum, 1);
        sum += __shfl_xor_sync(0xffffffffu, sum, 2);
        float mean = sum * (1.f / 64.f);
        float vs = 0.f;
#pragma unroll
        for (int i = 0; i < 16; i++) {
            vals[i] -= mean;
            vs += vals[i] * vals[i];
        }
        vs += __shfl_xor_sync(0xffffffffu, vs, 1);
        vs += __shfl_xor_sync(0xffffffffu, vs, 2);
        float inv = rsqrtf(vs * (1.f / 64.f) + 1e-5f);
        int off = (l0 + r_) * D + h * HD + cb_;
#pragma unroll
        for (int i = 0; i < 16; i += 2) {
            float v0 = vals[i] * inv, v1 = vals[i + 1] * inv;
            __nv_bfloat16 h0 = __float2bfloat16(v0);
            __nv_bfloat16 h1 = __float2bfloat16(v1);
            *(__nv_bfloat162*)&g_lnh[off + i] = __nv_bfloat162(h0, h1);
            *(__nv_bfloat162*)&g_lnl[off + i] = __nv_bfloat162(
                __float2bfloat16(v0 - __bfloat162float(h0)),
                __float2bfloat16(v1 - __bfloat162float(h1)));
        }
    }
}

// ---------------- launch ----------------------------------------------------
extern "C" void kernel_launch(void* const* d_in, const int* in_sizes, int n_in,
                              void* d_out, int out_size) {
    const float* X = (const float*)d_in[0];
    const float* Wq = (const float*)d_in[1];
    const float* Wk = (const float*)d_in[2];
    const float* Wv = (const float*)d_in[3];
    const float* Wu = (const float*)d_in[4];
    const float* Wg = (const float*)d_in[5];
    const float* Wo = (const float*)d_in[6];
    const float* pmu = (const float*)d_in[7];
    const float* plt = (const float*)d_in[8];
    float* out = (float*)d_out;

    cudaFuncSetAttribute(attn_tc, cudaFuncAttributeMaxDynamicSharedMemorySize,
                         ATTN_SMEM);
    cudaFuncSetAttribute(gemm_qkvu_tc, cudaFuncAttributeMaxDynamicSharedMemorySize,
                         GEMM_SMEM);
    cudaFuncSetAttribute(gemm_out_tc, cudaFuncAttributeMaxDynamicSharedMemorySize,
                         GEMM_SMEM);

    convert_inputs<<<dim3(96, 6), 256>>>(X, Wq, Wk, Wv, Wu, Wo);

    gemm_qkvu_tc<<<dim3(4 * D / GBN, L / GBM), 256, GEMM_SMEM>>>();
    gemm_gate<<<dim3(1, L / 64), 256>>>(X, Wg);

    cumsum_u_fast<<<D / 8, 256>>>();
    compute_s<<<(LH * 32 + 255) / 256, 256>>>(pmu, plt);
    head_scan<<<NH, 1024>>>();

    rope_norm<<<(LH * 32 + 255) / 256, 256>>>();

    // tensor-core attention + fused LayerNorm
    attn_tc<<<dim3(16, NH), 256, ATTN_SMEM>>>();

    gemm_out_tc<<<dim3(D / GBN, L / GBM), 256, GEMM_SMEM>>>(out);
}

// round 7
// speedup vs baseline: 3.3732x; 1.2500x over previous
#include <cuda_runtime.h>
#include <cuda_bf16.h>
#include <mma.h>
#include <math.h>
#include <cstdint>

using namespace nvcuda;

#define L 1024
#define D 768
#define NH 12
#define HD 64
#define LH (L*NH)

// ---------------- scratch (device globals; no allocation allowed) ----------
__device__ float g_q[L*D];
__device__ float g_k[L*D];
__device__ float g_v[L*D];
__device__ float g_u[L*D];
__device__ float g_usum[L*D];
__device__ float g_ct[4*D];      // per-chunk totals
__device__ float g_coff[4*D];    // per-chunk prefix offsets
__device__ float g_gatep[L*64];  // padded gate output (64-wide)
__device__ float g_s[LH];
__device__ float g_es[LH];
__device__ float g_al[LH];
__device__ float g_be[LH];
__device__ float g_ga[LH];

// split-bf16 buffers
__device__ __nv_bfloat16 g_Xh[L*D];
__device__ __nv_bfloat16 g_Xl[L*D];
__device__ __nv_bfloat16 g_Wh[5*D*D];   // Wq,Wk,Wv,Wu,Wo
__device__ __nv_bfloat16 g_Wl[5*D*D];
__device__ __nv_bfloat16 g_Wgph[64*D];  // Wg padded to 64 rows (zero-init)
__device__ __nv_bfloat16 g_Wgpl[64*D];
__device__ __nv_bfloat16 g_lnh[L*D];
__device__ __nv_bfloat16 g_lnl[L*D];
__device__ __nv_bfloat16 g_qh[L*D];
__device__ __nv_bfloat16 g_ql[L*D];
__device__ __nv_bfloat16 g_kh[L*D];
__device__ __nv_bfloat16 g_kl[L*D];
__device__ __nv_bfloat16 g_vh[L*D];
__device__ __nv_bfloat16 g_vl[L*D];

// ---------------- fp32 -> (hi, lo) bf16 conversion --------------------------
__global__ void convert_inputs(const float* __restrict__ X,
                               const float* __restrict__ Wq,
                               const float* __restrict__ Wk,
                               const float* __restrict__ Wv,
                               const float* __restrict__ Wu,
                               const float* __restrict__ Wo,
                               const float* __restrict__ Wg) {
    int z = blockIdx.y;
    const float* src;
    __nv_bfloat16 *dh, *dl;
    int n;
    if (z == 0) { src = X; dh = g_Xh; dl = g_Xl; n = L * D; }
    else if (z <= 5) {
        const float* ws[5] = {Wq, Wk, Wv, Wu, Wo};
        src = ws[z - 1];
        dh = g_Wh + (size_t)(z - 1) * D * D;
        dl = g_Wl + (size_t)(z - 1) * D * D;
        n = D * D;
    } else {
        src = Wg; dh = g_Wgph; dl = g_Wgpl; n = 36 * D;  // rows 36..63 stay 0
    }
    for (int i = blockIdx.x * blockDim.x + threadIdx.x; i < n;
         i += gridDim.x * blockDim.x) {
        float v = src[i];
        __nv_bfloat16 h = __float2bfloat16(v);
        dh[i] = h;
        dl[i] = __float2bfloat16(v - __bfloat162float(h));
    }
}

// ---------------- cp.async helpers ------------------------------------------
__device__ __forceinline__ void cp16(void* dst, const void* src) {
    unsigned d = (unsigned)__cvta_generic_to_shared(dst);
    asm volatile("cp.async.cg.shared.global [%0], [%1], 16;" :: "r"(d), "l"(src));
}

// ---------------- split-bf16 tensor-core GEMM (3-stage cp.async) ------------
#define GBM 128
#define GBN 64
#define GBK 64
#define GLD 72
#define GSTAGE 3
#define GEMM_SMEM ((GBM + GBN) * GLD * 2 * GSTAGE)   // 82944 bytes

__device__ __forceinline__ void gemm_stage_load(
    __nv_bfloat16* As, __nv_bfloat16* Bs,
    const __nv_bfloat16* __restrict__ A, const __nv_bfloat16* __restrict__ B,
    int m0, int n0, int kt, int tid) {
#pragma unroll
    for (int i = 0; i < 4; i++) {
        int idx = tid + i * 256;
        int r = idx >> 3, c8 = (idx & 7) * 8;
        cp16(&As[r * GLD + c8], &A[(size_t)(m0 + r) * D + kt + c8]);
    }
#pragma unroll
    for (int i = 0; i < 2; i++) {
        int idx = tid + i * 256;
        int r = idx >> 3, c8 = (idx & 7) * 8;
        cp16(&Bs[r * GLD + c8], &B[(size_t)(n0 + r) * D + kt + c8]);
    }
    asm volatile("cp.async.commit_group;");
}

__device__ __forceinline__ void gemm_body(
    const __nv_bfloat16* __restrict__ Ah, const __nv_bfloat16* __restrict__ Al,
    const __nv_bfloat16* __restrict__ Bh, const __nv_bfloat16* __restrict__ Bl,
    float* __restrict__ C, int m0, int n0, int Cld, int cn0) {
    extern __shared__ __nv_bfloat16 sh[];
    const int tid = threadIdx.x;
    const int warp = tid >> 5;
    const int wm = warp >> 1, wn = warp & 1;

    wmma::fragment<wmma::accumulator, 16, 16, 16, float> acc[2][2];
#pragma unroll
    for (int i = 0; i < 2; i++)
#pragma unroll
        for (int j = 0; j < 2; j++) wmma::fill_fragment(acc[i][j], 0.f);

    const int NIT = 36;  // 3 segments x 12 k-tiles
    auto stA = [&](int s) { return sh + (size_t)s * (GBM + GBN) * GLD; };
    auto stB = [&](int s) { return sh + (size_t)s * (GBM + GBN) * GLD + GBM * GLD; };
    auto getAB = [&](int it, const __nv_bfloat16*& A, const __nv_bfloat16*& B,
                     int& kt) {
        int seg = it / 12;
        kt = (it % 12) * GBK;
        A = (seg == 1) ? Al : Ah;
        B = (seg == 2) ? Bl : Bh;
    };

    {
        const __nv_bfloat16 *A, *B;
        int kt;
        getAB(0, A, B, kt);
        gemm_stage_load(stA(0), stB(0), A, B, m0, n0, kt, tid);
        getAB(1, A, B, kt);
        gemm_stage_load(stA(1), stB(1), A, B, m0, n0, kt, tid);
    }

#pragma unroll 1
    for (int it = 0; it < NIT; it++) {
        if (it < NIT - 1) asm volatile("cp.async.wait_group 1;");
        else              asm volatile("cp.async.wait_group 0;");
        __syncthreads();

        const __nv_bfloat16* As = stA(it % GSTAGE);
        const __nv_bfloat16* Bs = stB(it % GSTAGE);
#pragma unroll
        for (int kk = 0; kk < GBK; kk += 16) {
            wmma::fragment<wmma::matrix_a, 16, 16, 16, __nv_bfloat16,
                           wmma::row_major> a0, a1;
            wmma::fragment<wmma::matrix_b, 16, 16, 16, __nv_bfloat16,
                           wmma::col_major> b0, b1;
            wmma::load_matrix_sync(a0, &As[(wm * 32) * GLD + kk], GLD);
            wmma::load_matrix_sync(a1, &As[(wm * 32 + 16) * GLD + kk], GLD);
            wmma::load_matrix_sync(b0, &Bs[(wn * 32) * GLD + kk], GLD);
            wmma::load_matrix_sync(b1, &Bs[(wn * 32 + 16) * GLD + kk], GLD);
            wmma::mma_sync(acc[0][0], a0, b0, acc[0][0]);
            wmma::mma_sync(acc[0][1], a0, b1, acc[0][1]);
            wmma::mma_sync(acc[1][0], a1, b0, acc[1][0]);
            wmma::mma_sync(acc[1][1], a1, b1, acc[1][1]);
        }

        if (it + 2 < NIT) {
            const __nv_bfloat16 *A, *B;
            int kt;
            getAB(it + 2, A, B, kt);
            gemm_stage_load(stA((it + 2) % GSTAGE), stB((it + 2) % GSTAGE), A, B,
                            m0, n0, kt, tid);
        }
    }

#pragma unroll
    for (int i = 0; i < 2; i++)
#pragma unroll
        for (int j = 0; j < 2; j++)
            wmma::store_matrix_sync(
                &C[(size_t)(m0 + wm * 32 + i * 16) * Cld + cn0 + wn * 32 + j * 16],
                acc[i][j], Cld, wmma::mem_row_major);
}

// merged Q/K/V/U/gate projection: 49 n-blocks (48 qkvu + 1 gate)
__global__ void __launch_bounds__(256) gemm_qkvu_tc() {
    int bx = blockIdx.x;
    int m0 = blockIdx.y * GBM;
    if (bx < 48) {
        int nglob = bx * GBN;
        int z = nglob / D;
        int n0 = nglob % D;
        float* Cs[4] = {g_q, g_k, g_v, g_u};
        gemm_body(g_Xh, g_Xl, g_Wh + (size_t)z * D * D, g_Wl + (size_t)z * D * D,
                  Cs[z], m0, n0, D, n0);
    } else {
        gemm_body(g_Xh, g_Xl, g_Wgph, g_Wgpl, g_gatep, m0, 0, 64, 0);
    }
}

__global__ void __launch_bounds__(256) gemm_out_tc(float* __restrict__ out) {
    int n0 = blockIdx.x * GBN;
    gemm_body(g_lnh, g_lnl, g_Wh + (size_t)4 * D * D, g_Wl + (size_t)4 * D * D,
              out, blockIdx.y * GBM, n0, D, n0);
}

// ---------------- chunk-parallel cumsum of u over L -------------------------
__global__ void __launch_bounds__(256) cumsum_u_chunk() {
    __shared__ float sm[32][9];
    const int c0 = blockIdx.x * 8;
    const int base = blockIdx.y * 256;
    const int tid = threadIdx.x;
    const int w = tid >> 5, lane = tid & 31;
    const int lr = tid >> 3, lc = tid & 7;
    float carry = 0.f;
#pragma unroll 1
    for (int l0 = base; l0 < base + 256; l0 += 32) {
        float vin = g_u[(l0 + lr) * D + c0 + lc];
        __syncthreads();
        sm[lr][lc] = vin;
        __syncthreads();
        float v = sm[lane][w];
#pragma unroll
        for (int o = 1; o < 32; o <<= 1) {
            float n = __shfl_up_sync(0xffffffffu, v, o);
            if (lane >= o) v += n;
        }
        v += carry;
        carry = __shfl_sync(0xffffffffu, v, 31);
        sm[lane][w] = v;
        __syncthreads();
        g_usum[(l0 + lr) * D + c0 + lc] = sm[lr][lc];
    }
    if (lane == 0) g_ct[blockIdx.y * D + c0 + w] = carry;
}

__global__ void chunk_prefix() {
    int c = blockIdx.x * blockDim.x + threadIdx.x;
    if (c >= D) return;
    float t0 = g_ct[c], t1 = g_ct[D + c], t2 = g_ct[2 * D + c];
    g_coff[c] = 0.f;
    g_coff[D + c] = t0;
    g_coff[2 * D + c] = t0 + t1;
    g_coff[3 * D + c] = t0 + t1 + t2;
}

// ---------------- s_i = -(1/sqrt(d)) * u . bar_u ----------------------------
__global__ void compute_s(const float* __restrict__ pmu,
                          const float* __restrict__ plt) {
    int gw = (blockIdx.x * blockDim.x + threadIdx.x) >> 5;
    int lane = threadIdx.x & 31;
    if (gw >= LH) return;
    int l = gw / NH, h = gw % NH;
    float lt = expf(fminf(fmaxf(plt[h], -50.f), 30.f));
    float t = (float)(l + 1);
    float inv_den = 1.f / (lt + t);
    int chunk = l >> 8;
    float acc = 0.f;
#pragma unroll
    for (int r = 0; r < 2; r++) {
        int i = lane + r * 32;
        int ch = h * HD + i;
        float uu = g_u[l * D + ch];
        float us = g_usum[l * D + ch] + g_coff[chunk * D + ch];
        float bu = (lt * pmu[ch] + us) * inv_den;
        acc = fmaf(uu, bu, acc);
    }
#pragma unroll
    for (int o = 16; o; o >>= 1) acc += __shfl_xor_sync(0xffffffffu, acc, o);
    if (lane == 0) g_s[l * NH + h] = -acc * 0.125f;
}

// ---------------- per-head: max, scans, gate coefficients -------------------
__global__ void __launch_bounds__(1024) head_scan() {
    __shared__ float she[1024];
    __shared__ float shp[1024];
    const int h = blockIdx.x;
    const int l = threadIdx.x;
    float s = g_s[l * NH + h];
    she[l] = s;
    __syncthreads();
    for (int off = 512; off > 0; off >>= 1) {
        if (l < off) she[l] = fmaxf(she[l], she[l + off]);
        __syncthreads();
    }
    float smax = she[0];
    __syncthreads();
    float e = expf(s - smax);
    float ev = e, pv = s;
    she[l] = ev;
    shp[l] = pv;
    __syncthreads();
    for (int off = 1; off < 1024; off <<= 1) {
        float ae = 0.f, ap = 0.f;
        if (l >= off) { ae = she[l - off]; ap = shp[l - off]; }
        __syncthreads();
        ev += ae;
        pv += ap;
        she[l] = ev;
        shp[l] = pv;
        __syncthreads();
    }
    float g1 = g_gatep[l * 64 + h * 3 + 0];
    float gh = g_gatep[l * 64 + h * 3 + 1];
    float s1 = 1.f / (1.f + expf(-g1));
    float shg = 1.f / (1.f + expf(-gh));
    float t = (float)(l + 1);
    float a = shg / (ev + 1e-12f);
    float b = (s1 - shg) / t;
    float gm = -(b * pv + shg) / t;
    int o = l * NH + h;
    g_es[o] = e;
    g_al[o] = a;
    g_be[o] = b;
    g_ga[o] = gm;
}

// ---------------- RoPE + L2 normalize; emit split-bf16 q/k/v ----------------
__device__ __forceinline__ void split_store(__nv_bfloat16* dh, __nv_bfloat16* dl,
                                            int idx, float v) {
    __nv_bfloat16 hb = __float2bfloat16(v);
    dh[idx] = hb;
    dl[idx] = __float2bfloat16(v - __bfloat162float(hb));
}

__global__ void rope_norm() {
    int gw = (blockIdx.x * blockDim.x + threadIdx.x) >> 5;
    int lane = threadIdx.x & 31;
    if (gw >= LH) return;
    int l = gw / NH, h = gw % NH;
    int base = l * D + h * HD;
    int i0 = lane >> 1;
    const float LN1E4_32 = 0.28782313662425572f;
    float f0 = expf(-(float)i0 * LN1E4_32);
    float f1 = expf(-(float)(i0 + 16) * LN1E4_32);
    float a0 = (float)l * f0;
    float a1 = (float)l * f1;
    float c0 = cosf(a0), sn0 = sinf(a0);
    float c1 = cosf(a1), sn1 = sinf(a1);

    {
        float x0 = g_q[base + lane], x1 = g_q[base + lane + 32];
        float r0 = x0 * c0 - x1 * sn0;
        float r1 = x1 * c1 + x0 * sn1;
        float nn = r0 * r0 + r1 * r1;
#pragma unroll
        for (int o = 16; o; o >>= 1) nn += __shfl_xor_sync(0xffffffffu, nn, o);
        float inv = 1.f / fmaxf(sqrtf(nn), 1e-12f);
        split_store(g_qh, g_ql, base + lane, r0 * inv);
        split_store(g_qh, g_ql, base + lane + 32, r1 * inv);
    }
    {
        float x0 = g_k[base + lane], x1 = g_k[base + lane + 32];
        float r0 = x0 * c0 - x1 * sn0;
        float r1 = x1 * c1 + x0 * sn1;
        float nn = r0 * r0 + r1 * r1;
#pragma unroll
        for (int o = 16; o; o >>= 1) nn += __shfl_xor_sync(0xffffffffu, nn, o);
        float inv = 1.f / fmaxf(sqrtf(nn), 1e-12f);
        split_store(g_kh, g_kl, base + lane, r0 * inv);
        split_store(g_kh, g_kl, base + lane + 32, r1 * inv);
    }
    {
        split_store(g_vh, g_vl, base + lane, g_v[base + lane]);
        split_store(g_vh, g_vl, base + lane + 32, g_v[base + lane + 32]);
    }
}

// ---------------- tensor-core weighted causal attention + LayerNorm ---------
#define ALD 72
#define SLD 68
#define ATTN_SMEM (8 * 64 * ALD * 2 + 64 * SLD * 4)

__global__ void __launch_bounds__(256) attn_tc() {
    extern __shared__ __nv_bfloat16 ash[];
    __nv_bfloat16* Qh = ash;
    __nv_bfloat16* Ql = ash + 1 * 64 * ALD;
    __nv_bfloat16* Kh = ash + 2 * 64 * ALD;
    __nv_bfloat16* Kl = ash + 3 * 64 * ALD;
    __nv_bfloat16* Vh = ash + 4 * 64 * ALD;
    __nv_bfloat16* Vl = ash + 5 * 64 * ALD;
    __nv_bfloat16* Sh = ash + 6 * 64 * ALD;
    __nv_bfloat16* Sl = ash + 7 * 64 * ALD;
    float* Sf = (float*)(ash + 8 * 64 * ALD);
    __shared__ float cA[64], cB[64], cG[64], sES[64], sS[64];

    const int h = blockIdx.y;
    const int lt = 15 - blockIdx.x;
    const int l0 = lt * 64;
    const int tid = threadIdx.x;
    const int warp = tid >> 5;
    const int wm = warp >> 1, wn = warp & 1;

#pragma unroll
    for (int it = 0; it < 2; it++) {
        int idx = tid + it * 256;
        int r = idx >> 3, c = (idx & 7) * 8;
        *(uint4*)&Qh[r * ALD + c] = *(const uint4*)&g_qh[(l0 + r) * D + h * HD + c];
        *(uint4*)&Ql[r * ALD + c] = *(const uint4*)&g_ql[(l0 + r) * D + h * HD + c];
    }
    if (tid < 64) {
        cA[tid] = g_al[(l0 + tid) * NH + h];
        cB[tid] = g_be[(l0 + tid) * NH + h];
        cG[tid] = g_ga[(l0 + tid) * NH + h];
    }

    wmma::fragment<wmma::accumulator, 16, 16, 16, float> acc_o[2];
    wmma::fill_fragment(acc_o[0], 0.f);
    wmma::fill_fragment(acc_o[1], 0.f);

    const int r_ = tid >> 2;
    const int cb_ = (tid & 3) * 16;

#pragma unroll 1
    for (int jt = 0; jt <= lt; jt++) {
        const int j0 = jt * 64;
        __syncthreads();
#pragma unroll
        for (int it = 0; it < 2; it++) {
            int idx = tid + it * 256;
            int r = idx >> 3, c = (idx & 7) * 8;
            *(uint4*)&Kh[r * ALD + c] = *(const uint4*)&g_kh[(j0 + r) * D + h * HD + c];
            *(uint4*)&Kl[r * ALD + c] = *(const uint4*)&g_kl[(j0 + r) * D + h * HD + c];
            *(uint4*)&Vh[r * ALD + c] = *(const uint4*)&g_vh[(j0 + r) * D + h * HD + c];
            *(uint4*)&Vl[r * ALD + c] = *(const uint4*)&g_vl[(j0 + r) * D + h * HD + c];
        }
        if (tid < 64) {
            sES[tid] = g_es[(j0 + tid) * NH + h];
            sS[tid] = g_s[(j0 + tid) * NH + h];
        }
        __syncthreads();

        wmma::fragment<wmma::accumulator, 16, 16, 16, float> acc_s[2];
        wmma::fill_fragment(acc_s[0], 0.f);
        wmma::fill_fragment(acc_s[1], 0.f);
#pragma unroll
        for (int p = 0; p < 3; p++) {
            const __nv_bfloat16* Aq = (p == 1) ? Ql : Qh;
            const __nv_bfloat16* Bk = (p == 2) ? Kl : Kh;
#pragma unroll
            for (int kk = 0; kk < 64; kk += 16) {
                wmma::fragment<wmma::matrix_a, 16, 16, 16, __nv_bfloat16,
                               wmma::row_major> af;
                wmma::load_matrix_sync(af, &Aq[(wm * 16) * ALD + kk], ALD);
#pragma unroll
                for (int jn = 0; jn < 2; jn++) {
                    wmma::fragment<wmma::matrix_b, 16, 16, 16, __nv_bfloat16,
                                   wmma::col_major> bf;
                    wmma::load_matrix_sync(
                        bf, &Bk[(wn * 32 + jn * 16) * ALD + kk], ALD);
                    wmma::mma_sync(acc_s[jn], af, bf, acc_s[jn]);
                }
            }
        }
#pragma unroll
        for (int jn = 0; jn < 2; jn++)
            wmma::store_matrix_sync(&Sf[(wm * 16) * SLD + wn * 32 + jn * 16],
                                    acc_s[jn], SLD, wmma::mem_row_major);
        __syncthreads();

        {
            float Ar = cA[r_], Br = cB[r_], Gr = cG[r_];
            int gl = l0 + r_;
#pragma unroll
            for (int i = 0; i < 16; i++) {
                int c = cb_ + i;
                float w = Ar * sES[c] + Br * sS[c] + Gr;
                float sv = (j0 + c <= gl) ? Sf[r_ * SLD + c] * w : 0.f;
                __nv_bfloat16 hb = __float2bfloat16(sv);
                Sh[r_ * ALD + c] = hb;
                Sl[r_ * ALD + c] = __float2bfloat16(sv - __bfloat162float(hb));
            }
        }
        __syncthreads();

#pragma unroll
        for (int p = 0; p < 3; p++) {
            const __nv_bfloat16* Asm = (p == 1) ? Sl : Sh;
            const __nv_bfloat16* Bvm = (p == 2) ? Vl : Vh;
#pragma unroll
            for (int kk = 0; kk < 64; kk += 16) {
                wmma::fragment<wmma::matrix_a, 16, 16, 16, __nv_bfloat16,
                               wmma::row_major> af;
                wmma::load_matrix_sync(af, &Asm[(wm * 16) * ALD + kk], ALD);
#pragma unroll
                for (int jn = 0; jn < 2; jn++) {
                    wmma::fragment<wmma::matrix_b, 16, 16, 16, __nv_bfloat16,
                                   wmma::row_major> bf;
                    wmma::load_matrix_sync(bf, &Bvm[kk * ALD + wn * 32 + jn * 16],
                                           ALD);
                    wmma::mma_sync(acc_o[jn], af, bf, acc_o[jn]);
                }
            }
        }
    }

    __syncthreads();
#pragma unroll
    for (int jn = 0; jn < 2; jn++)
        wmma::store_matrix_sync(&Sf[(wm * 16) * SLD + wn * 32 + jn * 16],
                                acc_o[jn], SLD, wmma::mem_row_major);
    __syncthreads();
    {
        float vals[16];
        float sum = 0.f;
#pragma unroll
        for (int i = 0; i < 16; i++) {
            vals[i] = Sf[r_ * SLD + cb_ + i];
            sum += vals[i];
        }
        sum += __shfl_xor_sync(0xffffffffu, sum, 1);
        sum += __shfl_xor_sync(0xffffffffu, sum, 2);
        float mean = sum * (1.f / 64.f);
        float vs = 0.f;
#pragma unroll
        for (int i = 0; i < 16; i++) {
            vals[i] -= mean;
            vs += vals[i] * vals[i];
        }
        vs += __shfl_xor_sync(0xffffffffu, vs, 1);
        vs += __shfl_xor_sync(0xffffffffu, vs, 2);
        float inv = rsqrtf(vs * (1.f / 64.f) + 1e-5f);
        int off = (l0 + r_) * D + h * HD + cb_;
#pragma unroll
        for (int i = 0; i < 16; i += 2) {
            float v0 = vals[i] * inv, v1 = vals[i + 1] * inv;
            __nv_bfloat16 h0 = __float2bfloat16(v0);
            __nv_bfloat16 h1 = __float2bfloat16(v1);
            *(__nv_bfloat162*)&g_lnh[off + i] = __nv_bfloat162(h0, h1);
            *(__nv_bfloat162*)&g_lnl[off + i] = __nv_bfloat162(
                __float2bfloat16(v0 - __bfloat162float(h0)),
                __float2bfloat16(v1 - __bfloat162float(h1)));
        }
    }
}

// ---------------- launch ----------------------------------------------------
extern "C" void kernel_launch(void* const* d_in, const int* in_sizes, int n_in,
                              void* d_out, int out_size) {
    const float* X = (const float*)d_in[0];
    const float* Wq = (const float*)d_in[1];
    const float* Wk = (const float*)d_in[2];
    const float* Wv = (const float*)d_in[3];
    const float* Wu = (const float*)d_in[4];
    const float* Wg = (const float*)d_in[5];
    const float* Wo = (const float*)d_in[6];
    const float* pmu = (const float*)d_in[7];
    const float* plt = (const float*)d_in[8];
    float* out = (float*)d_out;

    cudaFuncSetAttribute(attn_tc, cudaFuncAttributeMaxDynamicSharedMemorySize,
                         ATTN_SMEM);
    cudaFuncSetAttribute(gemm_qkvu_tc, cudaFuncAttributeMaxDynamicSharedMemorySize,
                         GEMM_SMEM);
    cudaFuncSetAttribute(gemm_out_tc, cudaFuncAttributeMaxDynamicSharedMemorySize,
                         GEMM_SMEM);

    convert_inputs<<<dim3(96, 7), 256>>>(X, Wq, Wk, Wv, Wu, Wo, Wg);

    // merged Q/K/V/U + gate projection (49 n-blocks x 8 m-blocks)
    gemm_qkvu_tc<<<dim3(49, L / GBM), 256, GEMM_SMEM>>>();

    // logits pipeline (chunk-parallel cumsum)
    cumsum_u_chunk<<<dim3(D / 8, 4), 256>>>();
    chunk_prefix<<<3, 256>>>();
    compute_s<<<(LH * 32 + 255) / 256, 256>>>(pmu, plt);
    head_scan<<<NH, 1024>>>();

    rope_norm<<<(LH * 32 + 255) / 256, 256>>>();

    attn_tc<<<dim3(16, NH), 256, ATTN_SMEM>>>();

    gemm_out_tc<<<dim3(D / GBN, L / GBM), 256, GEMM_SMEM>>>(out);
}